// round 12
// baseline (speedup 1.0000x reference)
#include <cuda_runtime.h>
#include <cstdint>

// Problem constants
#define VSZ   32000
#define HSZ   512
#define BSZ   16
#define TSZ   128
#define G4    2048           // 4*H
#define NROW  2048           // T*B rows
#define OUT_HF 65536000      // B*T*V
#define OUT_CF 65544192      // + B*H

#define NRNN   32            // recurrence CTAs
#define NGRID  148
#define NT64   (VSZ / 64)    // 500 ntile jobs (64-wide N stripes)
#define NCHUNK 16            // 16 chunks of 8 timesteps (128 rows)

// ---------------- device scratch (no allocations allowed) ----------------
__device__ int      d_toks[NROW];
__device__ float    d_X [(size_t)NROW * HSZ];  // relu(emb[tok])       4 MB
__device__ float    d_Xg[(size_t)NROW * G4];   // X @ W_ih^T + b      16 MB
__device__ float    d_H2[(size_t)NROW * HSZ];  // all h2 (tf32-rounded) 4 MB
__device__ unsigned d_bar;                     // recurrence barrier counter
__device__ unsigned d_chunk;                   // published chunk count
__device__ unsigned d_job;                     // dynamic ntile job counter

// ---------------- helpers ----------------
__device__ __forceinline__ float tf32r(float x) {
    uint32_t u;
    asm("cvt.rna.tf32.f32 %0, %1;" : "=r"(u) : "f"(x));
    return __uint_as_float(u);
}
__device__ __forceinline__ uint32_t fbits(float x) { return __float_as_uint(x); }
__device__ __forceinline__ uint32_t s2u(const void* p) {
    return (uint32_t)__cvta_generic_to_shared(p);
}

__device__ __forceinline__ void mma8(float* d, const uint32_t* a, const uint32_t* b) {
    asm volatile(
        "mma.sync.aligned.m16n8k8.row.col.f32.tf32.tf32.f32 "
        "{%0,%1,%2,%3}, {%4,%5,%6,%7}, {%8,%9}, {%0,%1,%2,%3};"
        : "+f"(d[0]), "+f"(d[1]), "+f"(d[2]), "+f"(d[3])
        : "r"(a[0]), "r"(a[1]), "r"(a[2]), "r"(a[3]), "r"(b[0]), "r"(b[1]));
}

__device__ __forceinline__ void ldsm4(uint32_t* r, uint32_t addr) {
    asm volatile("ldmatrix.sync.aligned.m8n8.x4.shared.b16 {%0,%1,%2,%3}, [%4];"
                 : "=r"(r[0]), "=r"(r[1]), "=r"(r[2]), "=r"(r[3]) : "r"(addr));
}

__device__ __forceinline__ float sigf(float x) { return 1.0f / (1.0f + __expf(-x)); }

__device__ __forceinline__ unsigned ld_acq(const unsigned* p) {
    unsigned v;
    asm volatile("ld.global.acquire.gpu.u32 %0, [%1];" : "=r"(v) : "l"(p) : "memory");
    return v;
}

// ---------------- kernel 0: token prep (+ dtype detect, + counter reset) ----
__global__ void k_prep(const void* tgt) {
    __shared__ int nz;
    if (threadIdx.x == 0) nz = 0;
    __syncthreads();
    const unsigned* w = (const unsigned*)tgt;
    for (int i = threadIdx.x; i < 1024; i += blockDim.x)
        if (w[2 * i + 1] != 0u) atomicOr(&nz, 1);
    __syncthreads();
    bool is64 = (nz == 0);
    const long long* p64 = (const long long*)tgt;
    const int*       p32 = (const int*)tgt;
    for (int idx = threadIdx.x; idx < NROW; idx += blockDim.x) {
        int t = idx >> 4, b = idx & 15;
        int tok;
        if (t == 0) tok = 1;                      // BOS
        else {
            int s = b * TSZ + (t - 1);
            tok = is64 ? (int)p64[s] : p32[s];
        }
        d_toks[idx] = tok;
    }
    if (threadIdx.x == 0) { d_bar = 0u; d_chunk = 0u; d_job = 0u; }
}

// ---------------- kernel 1: embedding gather + ReLU ----------------
__global__ void k_gather(const float* __restrict__ emb) {
    int r = blockIdx.x;
    int tok = d_toks[r];
    const float4* src = (const float4*)(emb + (size_t)tok * HSZ);
    float4*       dst = (float4*)(d_X + (size_t)r * HSZ);
    float4 v = src[threadIdx.x];
    v.x = fmaxf(v.x, 0.f); v.y = fmaxf(v.y, 0.f);
    v.z = fmaxf(v.z, 0.f); v.w = fmaxf(v.w, 0.f);
    dst[threadIdx.x] = v;
}

// ---------------- kernel 2: Xg = X @ W_ih^T + (b_ih + b_hh) ----------------
__global__ __launch_bounds__(256)
void k_gemm0(const float* __restrict__ Bmat, const float* __restrict__ bias1,
             const float* __restrict__ bias2) {
    __shared__ float As[128][20];
    __shared__ float Bs[128][20];

    const float* A = d_X;
    float*       C = d_Xg;
    const int    N = G4;

    int tM = blockIdx.y, tN = blockIdx.x;
    int tid = threadIdx.x;
    int wid = tid >> 5, lane = tid & 31;
    int gid = lane >> 2, tig = lane & 3;
    int wm = wid >> 2, wn = wid & 3;

    float acc[4][4][4];
#pragma unroll
    for (int i = 0; i < 4; i++)
#pragma unroll
        for (int j = 0; j < 4; j++)
#pragma unroll
            for (int k = 0; k < 4; k++) acc[i][j][k] = 0.f;

    int rowL = tid >> 1;
    int kseg = (tid & 1) * 8;
    const float* Ap = A    + (size_t)(tM * 128 + rowL) * HSZ + kseg;
    const float* Bp = Bmat + (size_t)(tN * 128 + rowL) * HSZ + kseg;

    float4 pa0 = *(const float4*)(Ap);
    float4 pa1 = *(const float4*)(Ap + 4);
    float4 pb0 = *(const float4*)(Bp);
    float4 pb1 = *(const float4*)(Bp + 4);

    for (int kk = 0; kk < HSZ; kk += 16) {
        __syncthreads();
        *(float4*)&As[rowL][kseg]     = make_float4(tf32r(pa0.x), tf32r(pa0.y), tf32r(pa0.z), tf32r(pa0.w));
        *(float4*)&As[rowL][kseg + 4] = make_float4(tf32r(pa1.x), tf32r(pa1.y), tf32r(pa1.z), tf32r(pa1.w));
        *(float4*)&Bs[rowL][kseg]     = make_float4(tf32r(pb0.x), tf32r(pb0.y), tf32r(pb0.z), tf32r(pb0.w));
        *(float4*)&Bs[rowL][kseg + 4] = make_float4(tf32r(pb1.x), tf32r(pb1.y), tf32r(pb1.z), tf32r(pb1.w));
        __syncthreads();
        if (kk + 16 < HSZ) {
            pa0 = *(const float4*)(Ap + kk + 16);
            pa1 = *(const float4*)(Ap + kk + 20);
            pb0 = *(const float4*)(Bp + kk + 16);
            pb1 = *(const float4*)(Bp + kk + 20);
        }
#pragma unroll
        for (int k8 = 0; k8 < 16; k8 += 8) {
            uint32_t af[4][4], bf[4][2];
#pragma unroll
            for (int mf = 0; mf < 4; mf++) {
                int m = wm * 64 + mf * 16;
                af[mf][0] = fbits(As[m + gid]    [k8 + tig]);
                af[mf][1] = fbits(As[m + gid + 8][k8 + tig]);
                af[mf][2] = fbits(As[m + gid]    [k8 + tig + 4]);
                af[mf][3] = fbits(As[m + gid + 8][k8 + tig + 4]);
            }
#pragma unroll
            for (int nf = 0; nf < 4; nf++) {
                int n = wn * 32 + nf * 8;
                bf[nf][0] = fbits(Bs[n + gid][k8 + tig]);
                bf[nf][1] = fbits(Bs[n + gid][k8 + tig + 4]);
            }
#pragma unroll
            for (int mf = 0; mf < 4; mf++)
#pragma unroll
                for (int nf = 0; nf < 4; nf++) mma8(acc[mf][nf], af[mf], bf[nf]);
        }
    }

#pragma unroll
    for (int mf = 0; mf < 4; mf++) {
        int r0 = tM * 128 + wm * 64 + mf * 16 + gid;
        int r1 = r0 + 8;
#pragma unroll
        for (int nf = 0; nf < 4; nf++) {
            int cn = tN * 128 + wn * 32 + nf * 8 + tig * 2;
            float bv0 = bias1[cn] + bias2[cn];
            float bv1 = bias1[cn + 1] + bias2[cn + 1];
            *(float2*)(C + (size_t)r0 * N + cn) = make_float2(acc[mf][nf][0] + bv0, acc[mf][nf][1] + bv1);
            *(float2*)(C + (size_t)r1 * N + cn) = make_float2(acc[mf][nf][2] + bv0, acc[mf][nf][3] + bv1);
        }
    }
}

// ================== fused persistent kernel ==================
#define WS_STRIDE 516
#define HS_STRIDE 524
#define RNN_SMEM ((64 * WS_STRIDE + 16 * HS_STRIDE + 8 * 64 * 16) * 4)
#define BSTR 516  // resident B row stride (floats)
#define GSTR 36   // A stage row stride (floats)
// consumer smem need: (64*516 + 2*128*36)*4 = 168,960 B  <  RNN_SMEM = 198,400 B

// ---- consumer job: one 64-wide N stripe, B resident, chunks 0..15 paced ----
__device__ void consumer_job(float* sm, const float* __restrict__ Wout,
                             const float* __restrict__ bout,
                             float* __restrict__ out, int ntile) {
    float* Bres = sm;                      // [64][BSTR] resident W_out slab
    float* Abuf = sm + 64 * BSTR;          // [2][128*GSTR] A double buffer

    int tid = threadIdx.x;
    int wid = tid >> 5, lane = tid & 31;
    int wm = wid >> 2, wn = wid & 3;       // 2 x 4 warps -> 64 x 16 per warp
    int r8 = lane & 7, sq = lane >> 3;
    int gid = lane >> 2, tig = lane & 3;

    // load resident B tile (64 rows x 512), tf32-rounded, once per job
    for (int i4 = tid; i4 < 64 * 128; i4 += 256) {
        int r = i4 >> 7, k = (i4 & 127) * 4;
        float4 v = __ldg((const float4*)(Wout + (size_t)(ntile * 64 + r) * HSZ + k));
        *(float4*)&Bres[r * BSTR + k] =
            make_float4(tf32r(v.x), tf32r(v.y), tf32r(v.z), tf32r(v.w));
    }

    uint32_t a_off = (uint32_t)((((sq & 1) * 8 + r8) * GSTR + (sq >> 1) * 4) * 4);
    uint32_t b_off = (uint32_t)((((sq >> 1) * 8 + r8) * BSTR + (sq & 1) * 4) * 4);
    uint32_t abase0 = s2u(Abuf) + (uint32_t)(wm * 64 * GSTR * 4) + a_off;
    uint32_t bbase  = s2u(Bres) + (uint32_t)(wn * 16 * BSTR * 4) + b_off;

    int lrow = tid >> 1;
    int lcol = (tid & 1) * 16;
    __syncthreads();

    for (int chunk = 0; chunk < NCHUNK; chunk++) {
        if (tid == 0) {
            while (ld_acq(&d_chunk) <= (unsigned)chunk) __nanosleep(256);
        }
        __syncthreads();

        const float* Ap = d_H2 + (size_t)(chunk * 128 + lrow) * HSZ + lcol;

        float acc[4][2][4];
#pragma unroll
        for (int mf = 0; mf < 4; mf++)
#pragma unroll
            for (int nf = 0; nf < 2; nf++)
#pragma unroll
                for (int r = 0; r < 4; r++) acc[mf][nf][r] = 0.f;

        float4 ra[4];
#pragma unroll
        for (int i = 0; i < 4; i++) ra[i] = __ldcg((const float4*)(Ap + i * 4));
        {   // stage 0 -> buf 0 (d_H2 already tf32-rounded)
            float* as = Abuf + lrow * GSTR + lcol;
#pragma unroll
            for (int i = 0; i < 4; i++) *(float4*)(as + i * 4) = ra[i];
        }
        __syncthreads();

        for (int s = 0; s < 16; s++) {
            if (s < 15) {
                int k0 = (s + 1) * 32;
#pragma unroll
                for (int i = 0; i < 4; i++)
                    ra[i] = __ldcg((const float4*)(Ap + k0 + i * 4));
            }
            uint32_t asb = abase0 + (uint32_t)((s & 1) * 128 * GSTR * 4);
#pragma unroll
            for (int k8 = 0; k8 < 32; k8 += 8) {
                int kg = s * 32 + k8;              // global K for resident B
                uint32_t af[4][4], bf[4];
#pragma unroll
                for (int mf = 0; mf < 4; mf++)
                    ldsm4(af[mf], asb + (uint32_t)(mf * 16 * GSTR * 4) + (uint32_t)(k8 * 4));
                ldsm4(bf, bbase + (uint32_t)(kg * 4));
#pragma unroll
                for (int mf = 0; mf < 4; mf++) {
                    mma8(acc[mf][0], af[mf], &bf[0]);
                    mma8(acc[mf][1], af[mf], &bf[2]);
                }
            }
            if (s < 15) {
                __syncthreads();
                float* as = Abuf + ((s + 1) & 1) * 128 * GSTR + lrow * GSTR + lcol;
#pragma unroll
                for (int i = 0; i < 4; i++) *(float4*)(as + i * 4) = ra[i];
                __syncthreads();
            }
        }

        // epilogue: row r = t*B+b  ->  out row b*T+t
#pragma unroll
        for (int mf = 0; mf < 4; mf++) {
            int r0 = chunk * 128 + wm * 64 + mf * 16 + gid;
            int r1 = r0 + 8;
            int o0 = (r0 & 15) * TSZ + (r0 >> 4);
            int o1 = (r1 & 15) * TSZ + (r1 >> 4);
#pragma unroll
            for (int nf = 0; nf < 2; nf++) {
                int cn = ntile * 64 + wn * 16 + nf * 8 + tig * 2;
                float bv0 = bout[cn], bv1 = bout[cn + 1];
                *(float2*)(out + (size_t)o0 * VSZ + cn) =
                    make_float2(acc[mf][nf][0] + bv0, acc[mf][nf][1] + bv1);
                *(float2*)(out + (size_t)o1 * VSZ + cn) =
                    make_float2(acc[mf][nf][2] + bv0, acc[mf][nf][3] + bv1);
            }
        }
        __syncthreads();
    }
}

__global__ __launch_bounds__(256, 1)
void k_fused(const float* __restrict__ h0, const float* __restrict__ c0,
             const float* __restrict__ W_hh, const float* __restrict__ W_out,
             const float* __restrict__ b_out, float* __restrict__ out) {
    extern __shared__ float sm[];
    __shared__ int jslot;
    int tid = threadIdx.x;

    if (blockIdx.x < NRNN) {
        // -------- recurrence role (32 CTAs) — R8 structure, verbatim --------
        float* Wsh = sm;                                  // [64][516]
        float* hsh = sm + 64 * WS_STRIDE;                 // [16][524]
        float* red = hsh + 16 * HS_STRIDE;                // [8][64][16]

        int c = blockIdx.x;
        int wid = tid >> 5, lane = tid & 31, gid = lane >> 2, tig = lane & 3;
        int r8 = lane & 7, sq = lane >> 3;

        uint32_t w_off = (uint32_t)((((sq & 1) * 8 + r8) * WS_STRIDE + (sq >> 1) * 4) * 4);
        uint32_t h_off = (uint32_t)((((sq >> 1) * 8 + r8) * HS_STRIDE + (sq & 1) * 4) * 4);
        uint32_t wbase = s2u(Wsh) + w_off;
        uint32_t hbase = s2u(hsh) + h_off;

        for (int i = tid; i < 64 * HSZ; i += 256) {
            int lr = i >> 9, k = i & 511;
            int grow = (lr >> 4) * HSZ + c * 16 + (lr & 15);
            Wsh[lr * WS_STRIDE + k] = tf32r(W_hh[(size_t)grow * HSZ + k]);
        }

        int j = tid >> 4, b = tid & 15, dim = c * 16 + j;
        float creg = c0[b * HSZ + dim];

        for (int t = 0; t < TSZ; t++) {
            const float* hsrc = (t == 0) ? h0 : (d_H2 + (size_t)(t - 1) * (BSZ * HSZ));
            const float* xg = d_Xg + (size_t)(t * BSZ + b) * G4 + dim;
            float gx0 = __ldcs(xg);
            float gx1 = __ldcs(xg + HSZ);
            float gx2 = __ldcs(xg + 2 * HSZ);
            float gx3 = __ldcs(xg + 3 * HSZ);

            __syncthreads();
            for (int i4 = tid; i4 < (BSZ * HSZ) / 4; i4 += 256) {
                int bb = i4 >> 7;
                int kk = (i4 & 127) * 4;
                float4 v = __ldcg((const float4*)(hsrc + bb * HSZ + kk));
                v.x = tf32r(v.x); v.y = tf32r(v.y); v.z = tf32r(v.z); v.w = tf32r(v.w);
                *(float4*)&hsh[bb * HS_STRIDE + kk] = v;
            }
            __syncthreads();

            float acc[4][2][4];
#pragma unroll
            for (int mf = 0; mf < 4; mf++)
#pragma unroll
                for (int nf = 0; nf < 2; nf++)
#pragma unroll
                    for (int r = 0; r < 4; r++) acc[mf][nf][r] = 0.f;
            int kbase = wid * 64;
#pragma unroll
            for (int kf = 0; kf < 8; kf++) {
                int k0 = kbase + kf * 8;
                uint32_t bfr[4], af[4];
                ldsm4(bfr, hbase + (uint32_t)(k0 * 4));
#pragma unroll
                for (int mf = 0; mf < 4; mf++) {
                    ldsm4(af, wbase + (uint32_t)((mf * 16 * WS_STRIDE + k0) * 4));
                    mma8(acc[mf][0], af, &bfr[0]);
                    mma8(acc[mf][1], af, &bfr[2]);
                }
            }
#pragma unroll
            for (int mf = 0; mf < 4; mf++)
#pragma unroll
                for (int nf = 0; nf < 2; nf++)
#pragma unroll
                    for (int rg = 0; rg < 4; rg++) {
                        int lr = mf * 16 + gid + ((rg >= 2) ? 8 : 0);
                        int bb = nf * 8 + tig * 2 + (rg & 1);
                        red[(wid * 64 + lr) * 16 + bb] = acc[mf][nf][rg];
                    }
            __syncthreads();

            float g[4] = {gx0, gx1, gx2, gx3};
#pragma unroll
            for (int q = 0; q < 4; q++) {
                int lr = q * 16 + j;
#pragma unroll
                for (int w = 0; w < 8; w++) g[q] += red[(w * 64 + lr) * 16 + b];
            }
            float ig = sigf(g[0]), fg = sigf(g[1]), gg = tanhf(g[2]), og = sigf(g[3]);
            creg = fg * creg + ig * gg;
            float h2 = og * tanhf(creg);

            d_H2[(size_t)(t * BSZ + b) * HSZ + dim] = tf32r(h2);
            if (t == TSZ - 1) {
                out[OUT_HF + b * HSZ + dim] = h2;     // exact final states
                out[OUT_CF + b * HSZ + dim] = creg;
            }

            __syncthreads();
            if (t < TSZ - 1) {
                if (tid == 0) {
                    __threadfence();
                    atomicAdd(&d_bar, 1u);
                    unsigned target = 32u * (unsigned)(t + 1);
                    while (ld_acq(&d_bar) < target) { }
                    if (c == 0 && ((t + 1) & 7) == 0) {
                        __threadfence();
                        *(volatile unsigned*)&d_chunk = (unsigned)((t + 1) >> 3);
                    }
                }
                __syncthreads();
            }
        }

        // final chunk publication (chunk 15)
        if (tid == 0) {
            __threadfence();
            atomicAdd(&d_bar, 1u);
            if (c == 0) {
                while (ld_acq(&d_bar) < 32u * TSZ) { }
                __threadfence();
                *(volatile unsigned*)&d_chunk = (unsigned)NCHUNK;
            }
        }
        __syncthreads();
        // fall through: join consumer pool for the tail
    }

    // -------- consumer pool: dynamic ntile jobs (B resident per job) --------
    for (;;) {
        __syncthreads();
        if (tid == 0) jslot = (int)atomicAdd(&d_job, 1u);
        __syncthreads();
        int jb = jslot;
        if (jb >= NT64) break;
        consumer_job(sm, W_out, b_out, out, jb);
    }
}

// ---------------- launch ----------------
extern "C" void kernel_launch(void* const* d_in, const int* in_sizes, int n_in,
                              void* d_out, int out_size) {
    (void)in_sizes; (void)n_in; (void)out_size;
    const float* h0    = (const float*)d_in[1];
    const float* c0    = (const float*)d_in[2];
    const void*  tgt   = d_in[3];
    const float* emb   = (const float*)d_in[4];
    const float* W_ih  = (const float*)d_in[5];
    const float* W_hh  = (const float*)d_in[6];
    const float* b_ih  = (const float*)d_in[7];
    const float* b_hh  = (const float*)d_in[8];
    const float* W_out = (const float*)d_in[9];
    const float* b_out = (const float*)d_in[10];
    float* out = (float*)d_out;

    cudaFuncSetAttribute(k_fused, cudaFuncAttributeMaxDynamicSharedMemorySize, RNN_SMEM);

    k_prep<<<1, 256>>>(tgt);
    k_gather<<<NROW, 128>>>(emb);
    k_gemm0<<<dim3(G4 / 128, NROW / 128), 256>>>(W_ih, b_ih, b_hh);
    k_fused<<<NGRID, 256, RNN_SMEM>>>(h0, c0, W_hh, W_out, b_out, out);
}

// round 13
// speedup vs baseline: 1.6804x; 1.6804x over previous
#include <cuda_runtime.h>
#include <cstdint>

// Problem constants
#define VSZ   32000
#define HSZ   512
#define BSZ   16
#define TSZ   128
#define G4    2048           // 4*H
#define NROW  2048           // T*B rows
#define OUT_HF 65536000      // B*T*V
#define OUT_CF 65544192      // + B*H

#define NRNN   32            // recurrence CTAs
#define NGRID  148
#define NT     (VSZ / 128)   // 250 N-tiles
#define NCHUNK 16            // 16 chunks of 8 timesteps (128 rows)
#define NJOBS  (NCHUNK * NT) // 4000

// ---------------- device scratch (no allocations allowed) ----------------
__device__ int      d_toks[NROW];
__device__ float    d_X [(size_t)NROW * HSZ];  // relu(emb[tok])       4 MB
__device__ float    d_Xg[(size_t)NROW * G4];   // X @ W_ih^T + b      16 MB
__device__ float    d_H2[(size_t)NROW * HSZ];  // all h2 (tf32-rounded) 4 MB
__device__ unsigned d_bar;                     // recurrence barrier counter
__device__ unsigned d_chunk;                   // published chunk count
__device__ unsigned d_job;                     // dynamic job counter

// ---------------- helpers ----------------
__device__ __forceinline__ float tf32r(float x) {
    uint32_t u;
    asm("cvt.rna.tf32.f32 %0, %1;" : "=r"(u) : "f"(x));
    return __uint_as_float(u);
}
__device__ __forceinline__ uint32_t fbits(float x) { return __float_as_uint(x); }
__device__ __forceinline__ uint32_t s2u(const void* p) {
    return (uint32_t)__cvta_generic_to_shared(p);
}

__device__ __forceinline__ void mma8(float* d, const uint32_t* a, const uint32_t* b) {
    asm volatile(
        "mma.sync.aligned.m16n8k8.row.col.f32.tf32.tf32.f32 "
        "{%0,%1,%2,%3}, {%4,%5,%6,%7}, {%8,%9}, {%0,%1,%2,%3};"
        : "+f"(d[0]), "+f"(d[1]), "+f"(d[2]), "+f"(d[3])
        : "r"(a[0]), "r"(a[1]), "r"(a[2]), "r"(a[3]), "r"(b[0]), "r"(b[1]));
}

__device__ __forceinline__ void ldsm4(uint32_t* r, uint32_t addr) {
    asm volatile("ldmatrix.sync.aligned.m8n8.x4.shared.b16 {%0,%1,%2,%3}, [%4];"
                 : "=r"(r[0]), "=r"(r[1]), "=r"(r[2]), "=r"(r[3]) : "r"(addr));
}

__device__ __forceinline__ float sigf(float x) { return 1.0f / (1.0f + __expf(-x)); }

__device__ __forceinline__ unsigned ld_acq(const unsigned* p) {
    unsigned v;
    asm volatile("ld.global.acquire.gpu.u32 %0, [%1];" : "=r"(v) : "l"(p) : "memory");
    return v;
}

// ---------------- kernel 0: token prep (+ dtype detect, + counter reset) ----
__global__ void k_prep(const void* tgt) {
    __shared__ int nz;
    if (threadIdx.x == 0) nz = 0;
    __syncthreads();
    const unsigned* w = (const unsigned*)tgt;
    for (int i = threadIdx.x; i < 1024; i += blockDim.x)
        if (w[2 * i + 1] != 0u) atomicOr(&nz, 1);
    __syncthreads();
    bool is64 = (nz == 0);
    const long long* p64 = (const long long*)tgt;
    const int*       p32 = (const int*)tgt;
    for (int idx = threadIdx.x; idx < NROW; idx += blockDim.x) {
        int t = idx >> 4, b = idx & 15;
        int tok;
        if (t == 0) tok = 1;                      // BOS
        else {
            int s = b * TSZ + (t - 1);
            tok = is64 ? (int)p64[s] : p32[s];
        }
        d_toks[idx] = tok;
    }
    if (threadIdx.x == 0) { d_bar = 0u; d_chunk = 0u; d_job = 0u; }
}

// ---------------- kernel 1: embedding gather + ReLU ----------------
__global__ void k_gather(const float* __restrict__ emb) {
    int r = blockIdx.x;
    int tok = d_toks[r];
    const float4* src = (const float4*)(emb + (size_t)tok * HSZ);
    float4*       dst = (float4*)(d_X + (size_t)r * HSZ);
    float4 v = src[threadIdx.x];
    v.x = fmaxf(v.x, 0.f); v.y = fmaxf(v.y, 0.f);
    v.z = fmaxf(v.z, 0.f); v.w = fmaxf(v.w, 0.f);
    dst[threadIdx.x] = v;
}

// ---------------- kernel 2: Xg = X @ W_ih^T + (b_ih + b_hh) ----------------
__global__ __launch_bounds__(256)
void k_gemm0(const float* __restrict__ Bmat, const float* __restrict__ bias1,
             const float* __restrict__ bias2) {
    __shared__ float As[128][20];
    __shared__ float Bs[128][20];

    const float* A = d_X;
    float*       C = d_Xg;
    const int    N = G4;

    int tM = blockIdx.y, tN = blockIdx.x;
    int tid = threadIdx.x;
    int wid = tid >> 5, lane = tid & 31;
    int gid = lane >> 2, tig = lane & 3;
    int wm = wid >> 2, wn = wid & 3;

    float acc[4][4][4];
#pragma unroll
    for (int i = 0; i < 4; i++)
#pragma unroll
        for (int j = 0; j < 4; j++)
#pragma unroll
            for (int k = 0; k < 4; k++) acc[i][j][k] = 0.f;

    int rowL = tid >> 1;
    int kseg = (tid & 1) * 8;
    const float* Ap = A    + (size_t)(tM * 128 + rowL) * HSZ + kseg;
    const float* Bp = Bmat + (size_t)(tN * 128 + rowL) * HSZ + kseg;

    float4 pa0 = *(const float4*)(Ap);
    float4 pa1 = *(const float4*)(Ap + 4);
    float4 pb0 = *(const float4*)(Bp);
    float4 pb1 = *(const float4*)(Bp + 4);

    for (int kk = 0; kk < HSZ; kk += 16) {
        __syncthreads();
        *(float4*)&As[rowL][kseg]     = make_float4(tf32r(pa0.x), tf32r(pa0.y), tf32r(pa0.z), tf32r(pa0.w));
        *(float4*)&As[rowL][kseg + 4] = make_float4(tf32r(pa1.x), tf32r(pa1.y), tf32r(pa1.z), tf32r(pa1.w));
        *(float4*)&Bs[rowL][kseg]     = make_float4(tf32r(pb0.x), tf32r(pb0.y), tf32r(pb0.z), tf32r(pb0.w));
        *(float4*)&Bs[rowL][kseg + 4] = make_float4(tf32r(pb1.x), tf32r(pb1.y), tf32r(pb1.z), tf32r(pb1.w));
        __syncthreads();
        if (kk + 16 < HSZ) {
            pa0 = *(const float4*)(Ap + kk + 16);
            pa1 = *(const float4*)(Ap + kk + 20);
            pb0 = *(const float4*)(Bp + kk + 16);
            pb1 = *(const float4*)(Bp + kk + 20);
        }
#pragma unroll
        for (int k8 = 0; k8 < 16; k8 += 8) {
            uint32_t af[4][4], bf[4][2];
#pragma unroll
            for (int mf = 0; mf < 4; mf++) {
                int m = wm * 64 + mf * 16;
                af[mf][0] = fbits(As[m + gid]    [k8 + tig]);
                af[mf][1] = fbits(As[m + gid + 8][k8 + tig]);
                af[mf][2] = fbits(As[m + gid]    [k8 + tig + 4]);
                af[mf][3] = fbits(As[m + gid + 8][k8 + tig + 4]);
            }
#pragma unroll
            for (int nf = 0; nf < 4; nf++) {
                int n = wn * 32 + nf * 8;
                bf[nf][0] = fbits(Bs[n + gid][k8 + tig]);
                bf[nf][1] = fbits(Bs[n + gid][k8 + tig + 4]);
            }
#pragma unroll
            for (int mf = 0; mf < 4; mf++)
#pragma unroll
                for (int nf = 0; nf < 4; nf++) mma8(acc[mf][nf], af[mf], bf[nf]);
        }
    }

#pragma unroll
    for (int mf = 0; mf < 4; mf++) {
        int r0 = tM * 128 + wm * 64 + mf * 16 + gid;
        int r1 = r0 + 8;
#pragma unroll
        for (int nf = 0; nf < 4; nf++) {
            int cn = tN * 128 + wn * 32 + nf * 8 + tig * 2;
            float bv0 = bias1[cn] + bias2[cn];
            float bv1 = bias1[cn + 1] + bias2[cn + 1];
            *(float2*)(C + (size_t)r0 * N + cn) = make_float2(acc[mf][nf][0] + bv0, acc[mf][nf][1] + bv1);
            *(float2*)(C + (size_t)r1 * N + cn) = make_float2(acc[mf][nf][2] + bv0, acc[mf][nf][3] + bv1);
        }
    }
}

// ================== fused persistent kernel (512 threads / CTA) ==========
#define WS_STRIDE 516
#define HS_STRIDE 524
#define RNN_SMEM ((64 * WS_STRIDE + 16 * HS_STRIDE + 4 * 64 * 16) * 4)
#define GSTR 36   // consumer smem row stride (floats)

// ---- consumer: one 128x128 logits tile, 16 warps (32x32 each) ----
__device__ void gemm_tile_logits(float* sm, const float* __restrict__ Wout,
                                 const float* __restrict__ bout,
                                 float* __restrict__ out, int chunk, int ntile) {
    float* Abuf = sm;                      // [2][128*GSTR]
    float* Bbuf = sm + 2 * 128 * GSTR;     // [2][128*GSTR]

    int tid = threadIdx.x;
    int wid = tid >> 5, lane = tid & 31;
    int wm = wid >> 2, wn = wid & 3;       // 4 x 4 warps -> 32 x 32 tiles
    int r8 = lane & 7, sq = lane >> 3;

    uint32_t a_off = (uint32_t)((((sq & 1) * 8 + r8) * GSTR + (sq >> 1) * 4) * 4);
    uint32_t b_off = (uint32_t)((((sq >> 1) * 8 + r8) * GSTR + (sq & 1) * 4) * 4);
    uint32_t abase0 = s2u(Abuf) + (uint32_t)(wm * 32 * GSTR * 4) + a_off;
    uint32_t bbase0 = s2u(Bbuf) + (uint32_t)(wn * 32 * GSTR * 4) + b_off;

    int lrow = tid >> 2;                   // 0..127
    int lcol = (tid & 3) * 8;              // 0,8,16,24
    const float* Ap = d_H2 + (size_t)(chunk * 128 + lrow) * HSZ + lcol;
    const float* Bp = Wout + (size_t)(ntile * 128 + lrow) * HSZ + lcol;

    float4 ra[2], rb[2];
#pragma unroll
    for (int i = 0; i < 2; i++) {
        ra[i] = __ldcg((const float4*)(Ap + i * 4));   // already tf32-rounded
        rb[i] = __ldg((const float4*)(Bp + i * 4));
    }

    float acc[2][4][4];
#pragma unroll
    for (int i = 0; i < 2; i++)
#pragma unroll
        for (int j = 0; j < 4; j++)
#pragma unroll
            for (int k = 0; k < 4; k++) acc[i][j][k] = 0.f;

    {
        float* as = Abuf + lrow * GSTR + lcol;
        float* bs = Bbuf + lrow * GSTR + lcol;
#pragma unroll
        for (int i = 0; i < 2; i++) {
            *(float4*)(as + i * 4) = ra[i];
            *(float4*)(bs + i * 4) = make_float4(tf32r(rb[i].x), tf32r(rb[i].y), tf32r(rb[i].z), tf32r(rb[i].w));
        }
    }
    __syncthreads();

    for (int s = 0; s < 16; s++) {
        if (s < 15) {
            int k0 = (s + 1) * 32;
#pragma unroll
            for (int i = 0; i < 2; i++) {
                ra[i] = __ldcg((const float4*)(Ap + k0 + i * 4));
                rb[i] = __ldg((const float4*)(Bp + k0 + i * 4));
            }
        }
        uint32_t asb = abase0 + (uint32_t)((s & 1) * 128 * GSTR * 4);
        uint32_t bsb = bbase0 + (uint32_t)((s & 1) * 128 * GSTR * 4);
#pragma unroll
        for (int k8 = 0; k8 < 32; k8 += 8) {
            uint32_t af[2][4], bf[2][4];
#pragma unroll
            for (int mf = 0; mf < 2; mf++)
                ldsm4(af[mf], asb + (uint32_t)(mf * 16 * GSTR * 4) + (uint32_t)(k8 * 4));
            ldsm4(bf[0], bsb + (uint32_t)(k8 * 4));
            ldsm4(bf[1], bsb + (uint32_t)(16 * GSTR * 4) + (uint32_t)(k8 * 4));
#pragma unroll
            for (int mf = 0; mf < 2; mf++) {
                mma8(acc[mf][0], af[mf], &bf[0][0]);
                mma8(acc[mf][1], af[mf], &bf[0][2]);
                mma8(acc[mf][2], af[mf], &bf[1][0]);
                mma8(acc[mf][3], af[mf], &bf[1][2]);
            }
        }
        if (s < 15) {
            __syncthreads();
            float* as = Abuf + ((s + 1) & 1) * 128 * GSTR + lrow * GSTR + lcol;
            float* bs = Bbuf + ((s + 1) & 1) * 128 * GSTR + lrow * GSTR + lcol;
#pragma unroll
            for (int i = 0; i < 2; i++) {
                *(float4*)(as + i * 4) = ra[i];
                *(float4*)(bs + i * 4) = make_float4(tf32r(rb[i].x), tf32r(rb[i].y), tf32r(rb[i].z), tf32r(rb[i].w));
            }
            __syncthreads();
        }
    }

    // epilogue: row r = t*B+b  ->  out row b*T+t
    int gid = lane >> 2, tig = lane & 3;
#pragma unroll
    for (int mf = 0; mf < 2; mf++) {
        int r0 = chunk * 128 + wm * 32 + mf * 16 + gid;
        int r1 = r0 + 8;
        int o0 = (r0 & 15) * TSZ + (r0 >> 4);
        int o1 = (r1 & 15) * TSZ + (r1 >> 4);
#pragma unroll
        for (int nf = 0; nf < 4; nf++) {
            int cn = ntile * 128 + wn * 32 + nf * 8 + tig * 2;
            float bv0 = bout[cn], bv1 = bout[cn + 1];
            *(float2*)(out + (size_t)o0 * VSZ + cn) = make_float2(acc[mf][nf][0] + bv0, acc[mf][nf][1] + bv1);
            *(float2*)(out + (size_t)o1 * VSZ + cn) = make_float2(acc[mf][nf][2] + bv0, acc[mf][nf][3] + bv1);
        }
    }
}

__global__ __launch_bounds__(512, 1)
void k_fused(const float* __restrict__ h0, const float* __restrict__ c0,
             const float* __restrict__ W_hh, const float* __restrict__ W_out,
             const float* __restrict__ b_out, float* __restrict__ out) {
    extern __shared__ float sm[];
    __shared__ int jslot;
    int tid = threadIdx.x;

    if (blockIdx.x < NRNN) {
        // -------- recurrence role (32 CTAs, 16 warps) — R8 sync verbatim ----
        float* Wsh = sm;                                  // [64][516]
        float* hsh = sm + 64 * WS_STRIDE;                 // [16][524]
        float* red = hsh + 16 * HS_STRIDE;                // [4][64][16]

        int c = blockIdx.x;
        int wid = tid >> 5, lane = tid & 31, gid = lane >> 2, tig = lane & 3;
        int r8 = lane & 7, sq = lane >> 3;
        int mg = wid >> 2, kq = wid & 3;                  // M-group, K-quarter

        uint32_t w_off = (uint32_t)((((sq & 1) * 8 + r8) * WS_STRIDE + (sq >> 1) * 4) * 4);
        uint32_t h_off = (uint32_t)((((sq >> 1) * 8 + r8) * HS_STRIDE + (sq & 1) * 4) * 4);
        uint32_t wbase = s2u(Wsh) + w_off + (uint32_t)(mg * 16 * WS_STRIDE * 4);
        uint32_t hbase = s2u(hsh) + h_off;

        for (int i = tid; i < 64 * HSZ; i += 512) {
            int lr = i >> 9, k = i & 511;
            int grow = (lr >> 4) * HSZ + c * 16 + (lr & 15);
            Wsh[lr * WS_STRIDE + k] = tf32r(W_hh[(size_t)grow * HSZ + k]);
        }

        int j = tid >> 4, b = tid & 15, dim = c * 16 + (j & 15);
        float creg = 0.f;
        if (tid < 256) creg = c0[b * HSZ + dim];
        int kbase = kq * 128;

        for (int t = 0; t < TSZ; t++) {
            const float* hsrc = (t == 0) ? h0 : (d_H2 + (size_t)(t - 1) * (BSZ * HSZ));
            float gx0 = 0.f, gx1 = 0.f, gx2 = 0.f, gx3 = 0.f;
            if (tid < 256) {
                const float* xg = d_Xg + (size_t)(t * BSZ + b) * G4 + dim;
                gx0 = __ldcs(xg);
                gx1 = __ldcs(xg + HSZ);
                gx2 = __ldcs(xg + 2 * HSZ);
                gx3 = __ldcs(xg + 3 * HSZ);
            }

            __syncthreads();
            // stage h: 2048 float4 words, 512 threads -> 4 each
            for (int i4 = tid; i4 < (BSZ * HSZ) / 4; i4 += 512) {
                int bb = i4 >> 7;
                int kk = (i4 & 127) * 4;
                float4 v = __ldcg((const float4*)(hsrc + bb * HSZ + kk));
                v.x = tf32r(v.x); v.y = tf32r(v.y); v.z = tf32r(v.z); v.w = tf32r(v.w);
                *(float4*)&hsh[bb * HS_STRIDE + kk] = v;
            }
            __syncthreads();

            // MMA: warp = (M-group mg: 16 gate rows) x (K-quarter kq: 128 k)
            float acc[2][4];
#pragma unroll
            for (int nf = 0; nf < 2; nf++)
#pragma unroll
                for (int r = 0; r < 4; r++) acc[nf][r] = 0.f;
#pragma unroll
            for (int kf = 0; kf < 16; kf++) {
                int k0 = kbase + kf * 8;
                uint32_t bfr[4], af[4];
                ldsm4(bfr, hbase + (uint32_t)(k0 * 4));
                ldsm4(af, wbase + (uint32_t)(k0 * 4));
                mma8(acc[0], af, &bfr[0]);
                mma8(acc[1], af, &bfr[2]);
            }
#pragma unroll
            for (int nf = 0; nf < 2; nf++)
#pragma unroll
                for (int rg = 0; rg < 4; rg++) {
                    int lr = mg * 16 + gid + ((rg >= 2) ? 8 : 0);
                    int bb = nf * 8 + tig * 2 + (rg & 1);
                    red[(kq * 64 + lr) * 16 + bb] = acc[nf][rg];
                }
            __syncthreads();

            if (tid < 256) {
                float g[4] = {gx0, gx1, gx2, gx3};
#pragma unroll
                for (int q = 0; q < 4; q++) {
                    int lr = q * 16 + j;
#pragma unroll
                    for (int w = 0; w < 4; w++) g[q] += red[(w * 64 + lr) * 16 + b];
                }
                float ig = sigf(g[0]), fg = sigf(g[1]), gg = tanhf(g[2]), og = sigf(g[3]);
                creg = fg * creg + ig * gg;
                float h2 = og * tanhf(creg);

                d_H2[(size_t)(t * BSZ + b) * HSZ + dim] = tf32r(h2);
                if (t == TSZ - 1) {
                    out[OUT_HF + b * HSZ + dim] = h2;     // exact final states
                    out[OUT_CF + b * HSZ + dim] = creg;
                }
            }

            __syncthreads();
            if (t < TSZ - 1) {
                if (tid == 0) {
                    __threadfence();
                    atomicAdd(&d_bar, 1u);
                    unsigned target = 32u * (unsigned)(t + 1);
                    while (ld_acq(&d_bar) < target) { }
                    if (c == 0 && ((t + 1) & 7) == 0) {
                        __threadfence();
                        *(volatile unsigned*)&d_chunk = (unsigned)((t + 1) >> 3);
                    }
                }
                __syncthreads();
            }
        }

        // final chunk publication (chunk 15)
        if (tid == 0) {
            __threadfence();
            atomicAdd(&d_bar, 1u);
            if (c == 0) {
                while (ld_acq(&d_bar) < 32u * TSZ) { }
                __threadfence();
                *(volatile unsigned*)&d_chunk = (unsigned)NCHUNK;
            }
        }
        __syncthreads();
        // fall through: join consumer pool for the tail
    }

    // -------- consumer pool: dynamic (chunk, ntile) jobs ----------------
    for (;;) {
        __syncthreads();
        if (tid == 0) jslot = (int)atomicAdd(&d_job, 1u);
        __syncthreads();
        int jb = jslot;
        if (jb >= NJOBS) break;
        int chunk = jb / NT, ntile = jb % NT;
        if (tid == 0) {
            while (ld_acq(&d_chunk) <= (unsigned)chunk) __nanosleep(128);
        }
        __syncthreads();
        gemm_tile_logits(sm, W_out, b_out, out, chunk, ntile);
    }
}

// ---------------- launch ----------------
extern "C" void kernel_launch(void* const* d_in, const int* in_sizes, int n_in,
                              void* d_out, int out_size) {
    (void)in_sizes; (void)n_in; (void)out_size;
    const float* h0    = (const float*)d_in[1];
    const float* c0    = (const float*)d_in[2];
    const void*  tgt   = d_in[3];
    const float* emb   = (const float*)d_in[4];
    const float* W_ih  = (const float*)d_in[5];
    const float* W_hh  = (const float*)d_in[6];
    const float* b_ih  = (const float*)d_in[7];
    const float* b_hh  = (const float*)d_in[8];
    const float* W_out = (const float*)d_in[9];
    const float* b_out = (const float*)d_in[10];
    float* out = (float*)d_out;

    cudaFuncSetAttribute(k_fused, cudaFuncAttributeMaxDynamicSharedMemorySize, RNN_SMEM);

    k_prep<<<1, 256>>>(tgt);
    k_gather<<<NROW, 128>>>(emb);
    k_gemm0<<<dim3(G4 / 128, NROW / 128), 256>>>(W_ih, b_ih, b_hh);
    k_fused<<<NGRID, 512, RNN_SMEM>>>(h0, c0, W_hh, W_out, b_out, out);
}

// round 14
// speedup vs baseline: 1.7755x; 1.0566x over previous
#include <cuda_runtime.h>
#include <cstdint>

// Problem constants
#define VSZ   32000
#define HSZ   512
#define BSZ   16
#define TSZ   128
#define G4    2048           // 4*H
#define NROW  2048           // T*B rows
#define OUT_HF 65536000      // B*T*V
#define OUT_CF 65544192      // + B*H

#define NRNN   32            // recurrence CTAs
#define NGRID  148
#define NT     (VSZ / 128)   // 250 logits N-tiles
#define NCHUNK 16            // 16 chunks of 8 timesteps (128 rows)
#define NXG    256           // 16 tM x 16 tN Xg tiles
#define NJOBS  (NCHUNK * NT) // 4000 logits jobs
#define NTOT   (NXG + NJOBS)

// ---------------- device scratch (no allocations allowed) ----------------
__device__ int      d_toks[NROW];
__device__ float    d_X [(size_t)NROW * HSZ];  // relu(emb[tok])       4 MB
__device__ float    d_Xg[(size_t)NROW * G4];   // X @ W_ih^T + b      16 MB
__device__ float    d_H2[(size_t)NROW * HSZ];  // all h2 (tf32-rounded) 4 MB
__device__ __align__(128) unsigned d_bar4[128];// 4 barrier words, 128B apart
__device__ unsigned d_xgc[16];                 // per-tM Xg tile counters
__device__ unsigned d_chunk;                   // published chunk count
__device__ unsigned d_job;                     // dynamic job counter

// ---------------- helpers ----------------
__device__ __forceinline__ float tf32r(float x) {
    uint32_t u;
    asm("cvt.rna.tf32.f32 %0, %1;" : "=r"(u) : "f"(x));
    return __uint_as_float(u);
}
__device__ __forceinline__ uint32_t fbits(float x) { return __float_as_uint(x); }
__device__ __forceinline__ uint32_t s2u(const void* p) {
    return (uint32_t)__cvta_generic_to_shared(p);
}

__device__ __forceinline__ void mma8(float* d, const uint32_t* a, const uint32_t* b) {
    asm volatile(
        "mma.sync.aligned.m16n8k8.row.col.f32.tf32.tf32.f32 "
        "{%0,%1,%2,%3}, {%4,%5,%6,%7}, {%8,%9}, {%0,%1,%2,%3};"
        : "+f"(d[0]), "+f"(d[1]), "+f"(d[2]), "+f"(d[3])
        : "r"(a[0]), "r"(a[1]), "r"(a[2]), "r"(a[3]), "r"(b[0]), "r"(b[1]));
}

__device__ __forceinline__ void ldsm4(uint32_t* r, uint32_t addr) {
    asm volatile("ldmatrix.sync.aligned.m8n8.x4.shared.b16 {%0,%1,%2,%3}, [%4];"
                 : "=r"(r[0]), "=r"(r[1]), "=r"(r[2]), "=r"(r[3]) : "r"(addr));
}

__device__ __forceinline__ float sigf(float x) { return 1.0f / (1.0f + __expf(-x)); }

__device__ __forceinline__ unsigned ld_acq(const unsigned* p) {
    unsigned v;
    asm volatile("ld.global.acquire.gpu.u32 %0, [%1];" : "=r"(v) : "l"(p) : "memory");
    return v;
}

// ---------------- kernel 0: token prep (+ dtype detect, + counter reset) ----
__global__ void k_prep(const void* tgt) {
    __shared__ int nz;
    if (threadIdx.x == 0) nz = 0;
    __syncthreads();
    const unsigned* w = (const unsigned*)tgt;
    for (int i = threadIdx.x; i < 1024; i += blockDim.x)
        if (w[2 * i + 1] != 0u) atomicOr(&nz, 1);
    __syncthreads();
    bool is64 = (nz == 0);
    const long long* p64 = (const long long*)tgt;
    const int*       p32 = (const int*)tgt;
    for (int idx = threadIdx.x; idx < NROW; idx += blockDim.x) {
        int t = idx >> 4, b = idx & 15;
        int tok;
        if (t == 0) tok = 1;                      // BOS
        else {
            int s = b * TSZ + (t - 1);
            tok = is64 ? (int)p64[s] : p32[s];
        }
        d_toks[idx] = tok;
    }
    if (threadIdx.x < 128) d_bar4[threadIdx.x] = 0u;
    if (threadIdx.x < 16)  d_xgc[threadIdx.x] = 0u;
    if (threadIdx.x == 0) { d_chunk = 0u; d_job = 0u; }
}

// ---------------- kernel 1: embedding gather + ReLU ----------------
__global__ void k_gather(const float* __restrict__ emb) {
    int r = blockIdx.x;
    int tok = d_toks[r];
    const float4* src = (const float4*)(emb + (size_t)tok * HSZ);
    float4*       dst = (float4*)(d_X + (size_t)r * HSZ);
    float4 v = src[threadIdx.x];
    v.x = fmaxf(v.x, 0.f); v.y = fmaxf(v.y, 0.f);
    v.z = fmaxf(v.z, 0.f); v.w = fmaxf(v.w, 0.f);
    dst[threadIdx.x] = v;
}

// ================== fused persistent kernel (512 threads / CTA) ==========
#define WS_STRIDE 516
#define HS_STRIDE 524
#define RNN_SMEM ((64 * WS_STRIDE + 16 * HS_STRIDE + 4 * 64 * 16) * 4)
#define GSTR 36   // GEMM smem row stride (floats)

// ---- Xg tile: d_Xg[tM*128.., tN*128..] = X @ W_ih^T + (b_ih+b_hh) -------
__device__ void gemm_tile_xg(float* sm, const float* __restrict__ Wih,
                             const float* __restrict__ b1, const float* __restrict__ b2,
                             int tM, int tN) {
    float* Abuf = sm;                      // [2][128*GSTR]
    float* Bbuf = sm + 2 * 128 * GSTR;     // [2][128*GSTR]

    int tid = threadIdx.x;
    int wid = tid >> 5, lane = tid & 31;
    int wm = wid >> 2, wn = wid & 3;       // 4 x 4 warps -> 32 x 32 tiles
    int r8 = lane & 7, sq = lane >> 3;

    uint32_t a_off = (uint32_t)((((sq & 1) * 8 + r8) * GSTR + (sq >> 1) * 4) * 4);
    uint32_t b_off = (uint32_t)((((sq >> 1) * 8 + r8) * GSTR + (sq & 1) * 4) * 4);
    uint32_t abase0 = s2u(Abuf) + (uint32_t)(wm * 32 * GSTR * 4) + a_off;
    uint32_t bbase0 = s2u(Bbuf) + (uint32_t)(wn * 32 * GSTR * 4) + b_off;

    int lrow = tid >> 2;                   // 0..127
    int lcol = (tid & 3) * 8;              // 0,8,16,24
    const float* Ap = d_X + (size_t)(tM * 128 + lrow) * HSZ + lcol;
    const float* Bp = Wih + (size_t)(tN * 128 + lrow) * HSZ + lcol;

    float4 ra[2], rb[2];
#pragma unroll
    for (int i = 0; i < 2; i++) {
        ra[i] = __ldg((const float4*)(Ap + i * 4));
        rb[i] = __ldg((const float4*)(Bp + i * 4));
    }

    float acc[2][4][4];
#pragma unroll
    for (int i = 0; i < 2; i++)
#pragma unroll
        for (int j = 0; j < 4; j++)
#pragma unroll
            for (int k = 0; k < 4; k++) acc[i][j][k] = 0.f;

    {
        float* as = Abuf + lrow * GSTR + lcol;
        float* bs = Bbuf + lrow * GSTR + lcol;
#pragma unroll
        for (int i = 0; i < 2; i++) {
            *(float4*)(as + i * 4) = make_float4(tf32r(ra[i].x), tf32r(ra[i].y), tf32r(ra[i].z), tf32r(ra[i].w));
            *(float4*)(bs + i * 4) = make_float4(tf32r(rb[i].x), tf32r(rb[i].y), tf32r(rb[i].z), tf32r(rb[i].w));
        }
    }
    __syncthreads();

    for (int s = 0; s < 16; s++) {
        if (s < 15) {
            int k0 = (s + 1) * 32;
#pragma unroll
            for (int i = 0; i < 2; i++) {
                ra[i] = __ldg((const float4*)(Ap + k0 + i * 4));
                rb[i] = __ldg((const float4*)(Bp + k0 + i * 4));
            }
        }
        uint32_t asb = abase0 + (uint32_t)((s & 1) * 128 * GSTR * 4);
        uint32_t bsb = bbase0 + (uint32_t)((s & 1) * 128 * GSTR * 4);
#pragma unroll
        for (int k8 = 0; k8 < 32; k8 += 8) {
            uint32_t af[2][4], bf[2][4];
#pragma unroll
            for (int mf = 0; mf < 2; mf++)
                ldsm4(af[mf], asb + (uint32_t)(mf * 16 * GSTR * 4) + (uint32_t)(k8 * 4));
            ldsm4(bf[0], bsb + (uint32_t)(k8 * 4));
            ldsm4(bf[1], bsb + (uint32_t)(16 * GSTR * 4) + (uint32_t)(k8 * 4));
#pragma unroll
            for (int mf = 0; mf < 2; mf++) {
                mma8(acc[mf][0], af[mf], &bf[0][0]);
                mma8(acc[mf][1], af[mf], &bf[0][2]);
                mma8(acc[mf][2], af[mf], &bf[1][0]);
                mma8(acc[mf][3], af[mf], &bf[1][2]);
            }
        }
        if (s < 15) {
            __syncthreads();
            float* as = Abuf + ((s + 1) & 1) * 128 * GSTR + lrow * GSTR + lcol;
            float* bs = Bbuf + ((s + 1) & 1) * 128 * GSTR + lrow * GSTR + lcol;
#pragma unroll
            for (int i = 0; i < 2; i++) {
                *(float4*)(as + i * 4) = make_float4(tf32r(ra[i].x), tf32r(ra[i].y), tf32r(ra[i].z), tf32r(ra[i].w));
                *(float4*)(bs + i * 4) = make_float4(tf32r(rb[i].x), tf32r(rb[i].y), tf32r(rb[i].z), tf32r(rb[i].w));
            }
            __syncthreads();
        }
    }

    int gid = lane >> 2, tig = lane & 3;
#pragma unroll
    for (int mf = 0; mf < 2; mf++) {
        int r0 = tM * 128 + wm * 32 + mf * 16 + gid;
        int r1 = r0 + 8;
#pragma unroll
        for (int nf = 0; nf < 4; nf++) {
            int cn = tN * 128 + wn * 32 + nf * 8 + tig * 2;
            float bv0 = b1[cn] + b2[cn];
            float bv1 = b1[cn + 1] + b2[cn + 1];
            *(float2*)(d_Xg + (size_t)r0 * G4 + cn) = make_float2(acc[mf][nf][0] + bv0, acc[mf][nf][1] + bv1);
            *(float2*)(d_Xg + (size_t)r1 * G4 + cn) = make_float2(acc[mf][nf][2] + bv0, acc[mf][nf][3] + bv1);
        }
    }
}

// ---- logits tile: one 128x128 tile, 16 warps (32x32 each) ----
__device__ void gemm_tile_logits(float* sm, const float* __restrict__ Wout,
                                 const float* __restrict__ bout,
                                 float* __restrict__ out, int chunk, int ntile) {
    float* Abuf = sm;                      // [2][128*GSTR]
    float* Bbuf = sm + 2 * 128 * GSTR;     // [2][128*GSTR]

    int tid = threadIdx.x;
    int wid = tid >> 5, lane = tid & 31;
    int wm = wid >> 2, wn = wid & 3;       // 4 x 4 warps -> 32 x 32 tiles
    int r8 = lane & 7, sq = lane >> 3;

    uint32_t a_off = (uint32_t)((((sq & 1) * 8 + r8) * GSTR + (sq >> 1) * 4) * 4);
    uint32_t b_off = (uint32_t)((((sq >> 1) * 8 + r8) * GSTR + (sq & 1) * 4) * 4);
    uint32_t abase0 = s2u(Abuf) + (uint32_t)(wm * 32 * GSTR * 4) + a_off;
    uint32_t bbase0 = s2u(Bbuf) + (uint32_t)(wn * 32 * GSTR * 4) + b_off;

    int lrow = tid >> 2;                   // 0..127
    int lcol = (tid & 3) * 8;              // 0,8,16,24
    const float* Ap = d_H2 + (size_t)(chunk * 128 + lrow) * HSZ + lcol;
    const float* Bp = Wout + (size_t)(ntile * 128 + lrow) * HSZ + lcol;

    float4 ra[2], rb[2];
#pragma unroll
    for (int i = 0; i < 2; i++) {
        ra[i] = __ldcg((const float4*)(Ap + i * 4));   // already tf32-rounded
        rb[i] = __ldg((const float4*)(Bp + i * 4));
    }

    float acc[2][4][4];
#pragma unroll
    for (int i = 0; i < 2; i++)
#pragma unroll
        for (int j = 0; j < 4; j++)
#pragma unroll
            for (int k = 0; k < 4; k++) acc[i][j][k] = 0.f;

    {
        float* as = Abuf + lrow * GSTR + lcol;
        float* bs = Bbuf + lrow * GSTR + lcol;
#pragma unroll
        for (int i = 0; i < 2; i++) {
            *(float4*)(as + i * 4) = ra[i];
            *(float4*)(bs + i * 4) = make_float4(tf32r(rb[i].x), tf32r(rb[i].y), tf32r(rb[i].z), tf32r(rb[i].w));
        }
    }
    __syncthreads();

    for (int s = 0; s < 16; s++) {
        if (s < 15) {
            int k0 = (s + 1) * 32;
#pragma unroll
            for (int i = 0; i < 2; i++) {
                ra[i] = __ldcg((const float4*)(Ap + k0 + i * 4));
                rb[i] = __ldg((const float4*)(Bp + k0 + i * 4));
            }
        }
        uint32_t asb = abase0 + (uint32_t)((s & 1) * 128 * GSTR * 4);
        uint32_t bsb = bbase0 + (uint32_t)((s & 1) * 128 * GSTR * 4);
#pragma unroll
        for (int k8 = 0; k8 < 32; k8 += 8) {
            uint32_t af[2][4], bf[2][4];
#pragma unroll
            for (int mf = 0; mf < 2; mf++)
                ldsm4(af[mf], asb + (uint32_t)(mf * 16 * GSTR * 4) + (uint32_t)(k8 * 4));
            ldsm4(bf[0], bsb + (uint32_t)(k8 * 4));
            ldsm4(bf[1], bsb + (uint32_t)(16 * GSTR * 4) + (uint32_t)(k8 * 4));
#pragma unroll
            for (int mf = 0; mf < 2; mf++) {
                mma8(acc[mf][0], af[mf], &bf[0][0]);
                mma8(acc[mf][1], af[mf], &bf[0][2]);
                mma8(acc[mf][2], af[mf], &bf[1][0]);
                mma8(acc[mf][3], af[mf], &bf[1][2]);
            }
        }
        if (s < 15) {
            __syncthreads();
            float* as = Abuf + ((s + 1) & 1) * 128 * GSTR + lrow * GSTR + lcol;
            float* bs = Bbuf + ((s + 1) & 1) * 128 * GSTR + lrow * GSTR + lcol;
#pragma unroll
            for (int i = 0; i < 2; i++) {
                *(float4*)(as + i * 4) = ra[i];
                *(float4*)(bs + i * 4) = make_float4(tf32r(rb[i].x), tf32r(rb[i].y), tf32r(rb[i].z), tf32r(rb[i].w));
            }
            __syncthreads();
        }
    }

    // epilogue: row r = t*B+b  ->  out row b*T+t
    int gid = lane >> 2, tig = lane & 3;
#pragma unroll
    for (int mf = 0; mf < 2; mf++) {
        int r0 = chunk * 128 + wm * 32 + mf * 16 + gid;
        int r1 = r0 + 8;
        int o0 = (r0 & 15) * TSZ + (r0 >> 4);
        int o1 = (r1 & 15) * TSZ + (r1 >> 4);
#pragma unroll
        for (int nf = 0; nf < 4; nf++) {
            int cn = ntile * 128 + wn * 32 + nf * 8 + tig * 2;
            float bv0 = bout[cn], bv1 = bout[cn + 1];
            *(float2*)(out + (size_t)o0 * VSZ + cn) = make_float2(acc[mf][nf][0] + bv0, acc[mf][nf][1] + bv1);
            *(float2*)(out + (size_t)o1 * VSZ + cn) = make_float2(acc[mf][nf][2] + bv0, acc[mf][nf][3] + bv1);
        }
    }
}

__global__ __launch_bounds__(512, 1)
void k_fused(const float* __restrict__ h0, const float* __restrict__ c0,
             const float* __restrict__ W_hh, const float* __restrict__ W_ih,
             const float* __restrict__ b_ih, const float* __restrict__ b_hh,
             const float* __restrict__ W_out, const float* __restrict__ b_out,
             float* __restrict__ out) {
    extern __shared__ float sm[];
    __shared__ int jslot;
    int tid = threadIdx.x;

    if (blockIdx.x < NRNN) {
        // -------- recurrence role (32 CTAs, 16 warps) --------
        float* Wsh = sm;                                  // [64][516]
        float* hsh = sm + 64 * WS_STRIDE;                 // [16][524]
        float* red = hsh + 16 * HS_STRIDE;                // [4][64][16]

        int c = blockIdx.x;
        int wid = tid >> 5, lane = tid & 31, gid = lane >> 2, tig = lane & 3;
        int r8 = lane & 7, sq = lane >> 3;
        int mg = wid >> 2, kq = wid & 3;                  // M-group, K-quarter

        uint32_t w_off = (uint32_t)((((sq & 1) * 8 + r8) * WS_STRIDE + (sq >> 1) * 4) * 4);
        uint32_t h_off = (uint32_t)((((sq >> 1) * 8 + r8) * HS_STRIDE + (sq & 1) * 4) * 4);
        uint32_t wbase = s2u(Wsh) + w_off + (uint32_t)(mg * 16 * WS_STRIDE * 4);
        uint32_t hbase = s2u(hsh) + h_off;

        for (int i = tid; i < 64 * HSZ; i += 512) {
            int lr = i >> 9, k = i & 511;
            int grow = (lr >> 4) * HSZ + c * 16 + (lr & 15);
            Wsh[lr * WS_STRIDE + k] = tf32r(W_hh[(size_t)grow * HSZ + k]);
        }
        __syncthreads();

        int j = tid >> 4, b = tid & 15, dim = c * 16 + (j & 15);
        float creg = 0.f;
        if (tid < 256) creg = c0[b * HSZ + dim];
        int kbase = kq * 128;

        for (int t = 0; t < TSZ; t++) {
            // wait for the Xg row-block of this 8-step window (pool-produced)
            if ((t & 7) == 0) {
                if (tid == 0) {
                    while (ld_acq(&d_xgc[t >> 3]) < 16u) __nanosleep(64);
                }
                __syncthreads();
            }

            const float* hsrc = (t == 0) ? h0 : (d_H2 + (size_t)(t - 1) * (BSZ * HSZ));
            float gx0 = 0.f, gx1 = 0.f, gx2 = 0.f, gx3 = 0.f;
            if (tid < 256) {
                const float* xg = d_Xg + (size_t)(t * BSZ + b) * G4 + dim;
                gx0 = __ldcs(xg);
                gx1 = __ldcs(xg + HSZ);
                gx2 = __ldcs(xg + 2 * HSZ);
                gx3 = __ldcs(xg + 3 * HSZ);
            }

            // stage h: 2048 float4 words, 512 threads -> 4 each
            for (int i4 = tid; i4 < (BSZ * HSZ) / 4; i4 += 512) {
                int bb = i4 >> 7;
                int kk = (i4 & 127) * 4;
                float4 v = __ldcg((const float4*)(hsrc + bb * HSZ + kk));
                v.x = tf32r(v.x); v.y = tf32r(v.y); v.z = tf32r(v.z); v.w = tf32r(v.w);
                *(float4*)&hsh[bb * HS_STRIDE + kk] = v;
            }
            __syncthreads();

            // MMA: warp = (M-group mg: 16 gate rows) x (K-quarter kq: 128 k)
            float acc[2][4];
#pragma unroll
            for (int nf = 0; nf < 2; nf++)
#pragma unroll
                for (int r = 0; r < 4; r++) acc[nf][r] = 0.f;
#pragma unroll
            for (int kf = 0; kf < 16; kf++) {
                int k0 = kbase + kf * 8;
                uint32_t bfr[4], af[4];
                ldsm4(bfr, hbase + (uint32_t)(k0 * 4));
                ldsm4(af, wbase + (uint32_t)(k0 * 4));
                mma8(acc[0], af, &bfr[0]);
                mma8(acc[1], af, &bfr[2]);
            }
#pragma unroll
            for (int nf = 0; nf < 2; nf++)
#pragma unroll
                for (int rg = 0; rg < 4; rg++) {
                    int lr = mg * 16 + gid + ((rg >= 2) ? 8 : 0);
                    int bb = nf * 8 + tig * 2 + (rg & 1);
                    red[(kq * 64 + lr) * 16 + bb] = acc[nf][rg];
                }
            __syncthreads();

            if (tid < 256) {
                float g[4] = {gx0, gx1, gx2, gx3};
#pragma unroll
                for (int q = 0; q < 4; q++) {
                    int lr = q * 16 + j;
#pragma unroll
                    for (int w = 0; w < 4; w++) g[q] += red[(w * 64 + lr) * 16 + b];
                }
                float ig = sigf(g[0]), fg = sigf(g[1]), gg = tanhf(g[2]), og = sigf(g[3]);
                creg = fg * creg + ig * gg;
                float h2 = og * tanhf(creg);

                d_H2[(size_t)(t * BSZ + b) * HSZ + dim] = tf32r(h2);
                if (t == TSZ - 1) {
                    out[OUT_HF + b * HSZ + dim] = h2;     // exact final states
                    out[OUT_CF + b * HSZ + dim] = creg;
                }
            }
            __syncthreads();

            // 4-way split barrier: CTA group (c>>3) increments its own word
            if (tid == 0) {
                __threadfence();
                atomicAdd(&d_bar4[(c >> 3) << 5], 1u);
            }
            if (t < TSZ - 1) {
                unsigned target = 8u * (unsigned)(t + 1);
                if (tid < 4) {
                    while (ld_acq(&d_bar4[tid << 5]) < target) { }
                }
                __syncthreads();
                if (c == 0 && tid == 0 && ((t + 1) & 7) == 0) {
                    __threadfence();
                    *(volatile unsigned*)&d_chunk = (unsigned)((t + 1) >> 3);
                }
            }
        }

        // final chunk publication (chunk 15)
        if (c == 0) {
            if (tid < 4) {
                while (ld_acq(&d_bar4[tid << 5]) < 8u * (unsigned)TSZ) { }
            }
            __syncthreads();
            if (tid == 0) {
                __threadfence();
                *(volatile unsigned*)&d_chunk = (unsigned)NCHUNK;
            }
        }
        __syncthreads();
        // fall through: join consumer pool for the tail
    }

    // -------- job pool: 256 Xg tiles first, then 4000 logits tiles --------
    for (;;) {
        __syncthreads();
        if (tid == 0) jslot = (int)atomicAdd(&d_job, 1u);
        __syncthreads();
        int jb = jslot;
        if (jb >= NTOT) break;
        if (jb < NXG) {
            int tM = jb >> 4, tN = jb & 15;
            gemm_tile_xg(sm, W_ih, b_ih, b_hh, tM, tN);
            __syncthreads();
            if (tid == 0) {
                __threadfence();
                atomicAdd(&d_xgc[tM], 1u);
            }
        } else {
            int q = jb - NXG;
            int chunk = q / NT, ntile = q % NT;
            if (tid == 0) {
                while (ld_acq(&d_chunk) <= (unsigned)chunk) __nanosleep(128);
            }
            __syncthreads();
            gemm_tile_logits(sm, W_out, b_out, out, chunk, ntile);
        }
    }
}

// ---------------- launch ----------------
extern "C" void kernel_launch(void* const* d_in, const int* in_sizes, int n_in,
                              void* d_out, int out_size) {
    (void)in_sizes; (void)n_in; (void)out_size;
    const float* h0    = (const float*)d_in[1];
    const float* c0    = (const float*)d_in[2];
    const void*  tgt   = d_in[3];
    const float* emb   = (const float*)d_in[4];
    const float* W_ih  = (const float*)d_in[5];
    const float* W_hh  = (const float*)d_in[6];
    const float* b_ih  = (const float*)d_in[7];
    const float* b_hh  = (const float*)d_in[8];
    const float* W_out = (const float*)d_in[9];
    const float* b_out = (const float*)d_in[10];
    float* out = (float*)d_out;

    cudaFuncSetAttribute(k_fused, cudaFuncAttributeMaxDynamicSharedMemorySize, RNN_SMEM);

    k_prep<<<1, 256>>>(tgt);
    k_gather<<<NROW, 128>>>(emb);
    k_fused<<<NGRID, 512, RNN_SMEM>>>(h0, c0, W_hh, W_ih, b_ih, b_hh, W_out, b_out, out);
}

// round 16
// speedup vs baseline: 1.8295x; 1.0304x over previous
#include <cuda_runtime.h>
#include <cstdint>

// Problem constants
#define VSZ   32000
#define HSZ   512
#define BSZ   16
#define TSZ   128
#define G4    2048           // 4*H
#define NROW  2048           // T*B rows
#define OUT_HF 65536000      // B*T*V
#define OUT_CF 65544192      // + B*H

#define NRNN   32            // recurrence CTAs
#define NGRID  148
#define NT     (VSZ / 128)   // 250 logits N-tiles
#define NCHUNK 16            // 16 chunks of 8 timesteps (128 rows)
#define NGATH  16            // 16 gather jobs (128 rows each)
#define NXG    256           // 16 tM x 16 tN Xg tiles
#define NJOBS  (NCHUNK * NT) // 4000 logits jobs
#define NTOT   (NGATH + NXG + NJOBS)

// ---------------- device scratch (no allocations allowed) ----------------
__device__ int      d_toks[NROW];
__device__ float    d_X [(size_t)NROW * HSZ];  // relu(emb[tok])       4 MB
// transposed gates: idx = ((t*32 + c)*4 + q)*256 + j*16 + b   (16 MB)
__device__ float    d_Xg[(size_t)TSZ * 32 * 4 * 256];
__device__ float    d_H2[(size_t)NROW * HSZ];  // all h2 (tf32-rounded) 4 MB
__device__ __align__(128) unsigned d_bar4[128];// 4 barrier words, 128B apart
__device__ unsigned d_gc[16];                  // gather-done flags
__device__ unsigned d_xgc[16];                 // per-tM Xg tile counters
__device__ unsigned d_chunk;                   // published chunk count
__device__ unsigned d_job;                     // dynamic job counter

// ---------------- helpers ----------------
__device__ __forceinline__ float tf32r(float x) {
    uint32_t u;
    asm("cvt.rna.tf32.f32 %0, %1;" : "=r"(u) : "f"(x));
    return __uint_as_float(u);
}
__device__ __forceinline__ uint32_t fbits(float x) { return __float_as_uint(x); }
__device__ __forceinline__ uint32_t s2u(const void* p) {
    return (uint32_t)__cvta_generic_to_shared(p);
}

__device__ __forceinline__ void mma8(float* d, const uint32_t* a, const uint32_t* b) {
    asm volatile(
        "mma.sync.aligned.m16n8k8.row.col.f32.tf32.tf32.f32 "
        "{%0,%1,%2,%3}, {%4,%5,%6,%7}, {%8,%9}, {%0,%1,%2,%3};"
        : "+f"(d[0]), "+f"(d[1]), "+f"(d[2]), "+f"(d[3])
        : "r"(a[0]), "r"(a[1]), "r"(a[2]), "r"(a[3]), "r"(b[0]), "r"(b[1]));
}

__device__ __forceinline__ void ldsm4(uint32_t* r, uint32_t addr) {
    asm volatile("ldmatrix.sync.aligned.m8n8.x4.shared.b16 {%0,%1,%2,%3}, [%4];"
                 : "=r"(r[0]), "=r"(r[1]), "=r"(r[2]), "=r"(r[3]) : "r"(addr));
}

__device__ __forceinline__ float sigf(float x) { return 1.0f / (1.0f + __expf(-x)); }

__device__ __forceinline__ unsigned ld_acq(const unsigned* p) {
    unsigned v;
    asm volatile("ld.global.acquire.gpu.u32 %0, [%1];" : "=r"(v) : "l"(p) : "memory");
    return v;
}
__device__ __forceinline__ void st_rel(unsigned* p, unsigned v) {
    asm volatile("st.global.release.gpu.u32 [%0], %1;" :: "l"(p), "r"(v) : "memory");
}

// ---------------- kernel 0: token prep (+ dtype detect, + counter reset) ----
__global__ void k_prep(const void* tgt) {
    __shared__ int nz;
    if (threadIdx.x == 0) nz = 0;
    __syncthreads();
    const unsigned* w = (const unsigned*)tgt;
    for (int i = threadIdx.x; i < 1024; i += blockDim.x)
        if (w[2 * i + 1] != 0u) atomicOr(&nz, 1);
    __syncthreads();
    bool is64 = (nz == 0);
    const long long* p64 = (const long long*)tgt;
    const int*       p32 = (const int*)tgt;
    for (int idx = threadIdx.x; idx < NROW; idx += blockDim.x) {
        int t = idx >> 4, b = idx & 15;
        int tok;
        if (t == 0) tok = 1;                      // BOS
        else {
            int s = b * TSZ + (t - 1);
            tok = is64 ? (int)p64[s] : p32[s];
        }
        d_toks[idx] = tok;
    }
    if (threadIdx.x < 128) d_bar4[threadIdx.x] = 0u;
    if (threadIdx.x < 16)  { d_gc[threadIdx.x] = 0u; d_xgc[threadIdx.x] = 0u; }
    if (threadIdx.x == 0)  { d_chunk = 0u; d_job = 0u; }
}

// ================== fused persistent kernel (512 threads / CTA) ==========
#define WS_STRIDE 516
#define HS_STRIDE 524
#define RNN_SMEM ((64 * WS_STRIDE + 16 * HS_STRIDE + 4 * 64 * 16) * 4)
#define GSTR 36   // GEMM smem row stride (floats)

// ---- gather job g: rows [g*128, g*128+128) of X = relu(emb[tok]) --------
__device__ void gather_job(const float* __restrict__ emb, int g) {
    int tid = threadIdx.x;
    for (int i = tid; i < 128 * 128; i += 512) {       // 16384 float4
        int r = g * 128 + (i >> 7);
        int kk = (i & 127);
        int tok = d_toks[r];
        float4 v = __ldg((const float4*)(emb + (size_t)tok * HSZ) + kk);
        v.x = fmaxf(v.x, 0.f); v.y = fmaxf(v.y, 0.f);
        v.z = fmaxf(v.z, 0.f); v.w = fmaxf(v.w, 0.f);
        ((float4*)(d_X + (size_t)r * HSZ))[kk] = v;
    }
}

// ---- Xg tile (tM,tN): rows tM*128..+128, cols tN*128..+128, transposed out
// NOTE: d_X is written by gather jobs within THIS kernel -> must use the
// coherent load path (__ldcg), NOT __ldg/ld.global.nc.
__device__ void gemm_tile_xg(float* sm, const float* __restrict__ Wih,
                             const float* __restrict__ b1, const float* __restrict__ b2,
                             int tM, int tN) {
    float* Abuf = sm;                      // [2][128*GSTR]
    float* Bbuf = sm + 2 * 128 * GSTR;     // [2][128*GSTR]

    int tid = threadIdx.x;
    int wid = tid >> 5, lane = tid & 31;
    int wm = wid >> 2, wn = wid & 3;       // 4 x 4 warps -> 32 x 32 tiles
    int r8 = lane & 7, sq = lane >> 3;

    uint32_t a_off = (uint32_t)((((sq & 1) * 8 + r8) * GSTR + (sq >> 1) * 4) * 4);
    uint32_t b_off = (uint32_t)((((sq >> 1) * 8 + r8) * GSTR + (sq & 1) * 4) * 4);
    uint32_t abase0 = s2u(Abuf) + (uint32_t)(wm * 32 * GSTR * 4) + a_off;
    uint32_t bbase0 = s2u(Bbuf) + (uint32_t)(wn * 32 * GSTR * 4) + b_off;

    int lrow = tid >> 2;                   // 0..127
    int lcol = (tid & 3) * 8;              // 0,8,16,24
    const float* Ap = d_X + (size_t)(tM * 128 + lrow) * HSZ + lcol;
    const float* Bp = Wih + (size_t)(tN * 128 + lrow) * HSZ + lcol;

    float4 ra[2], rb[2];
#pragma unroll
    for (int i = 0; i < 2; i++) {
        ra[i] = __ldcg((const float4*)(Ap + i * 4));   // coherent (intra-kernel producer)
        rb[i] = __ldg((const float4*)(Bp + i * 4));
    }

    float acc[2][4][4];
#pragma unroll
    for (int i = 0; i < 2; i++)
#pragma unroll
        for (int j = 0; j < 4; j++)
#pragma unroll
            for (int k = 0; k < 4; k++) acc[i][j][k] = 0.f;

    {
        float* as = Abuf + lrow * GSTR + lcol;
        float* bs = Bbuf + lrow * GSTR + lcol;
#pragma unroll
        for (int i = 0; i < 2; i++) {
            *(float4*)(as + i * 4) = make_float4(tf32r(ra[i].x), tf32r(ra[i].y), tf32r(ra[i].z), tf32r(ra[i].w));
            *(float4*)(bs + i * 4) = make_float4(tf32r(rb[i].x), tf32r(rb[i].y), tf32r(rb[i].z), tf32r(rb[i].w));
        }
    }
    __syncthreads();

    for (int s = 0; s < 16; s++) {
        if (s < 15) {
            int k0 = (s + 1) * 32;
#pragma unroll
            for (int i = 0; i < 2; i++) {
                ra[i] = __ldcg((const float4*)(Ap + k0 + i * 4));
                rb[i] = __ldg((const float4*)(Bp + k0 + i * 4));
            }
        }
        uint32_t asb = abase0 + (uint32_t)((s & 1) * 128 * GSTR * 4);
        uint32_t bsb = bbase0 + (uint32_t)((s & 1) * 128 * GSTR * 4);
#pragma unroll
        for (int k8 = 0; k8 < 32; k8 += 8) {
            uint32_t af[2][4], bf[2][4];
#pragma unroll
            for (int mf = 0; mf < 2; mf++)
                ldsm4(af[mf], asb + (uint32_t)(mf * 16 * GSTR * 4) + (uint32_t)(k8 * 4));
            ldsm4(bf[0], bsb + (uint32_t)(k8 * 4));
            ldsm4(bf[1], bsb + (uint32_t)(16 * GSTR * 4) + (uint32_t)(k8 * 4));
#pragma unroll
            for (int mf = 0; mf < 2; mf++) {
                mma8(acc[mf][0], af[mf], &bf[0][0]);
                mma8(acc[mf][1], af[mf], &bf[0][2]);
                mma8(acc[mf][2], af[mf], &bf[1][0]);
                mma8(acc[mf][3], af[mf], &bf[1][2]);
            }
        }
        if (s < 15) {
            __syncthreads();
            float* as = Abuf + ((s + 1) & 1) * 128 * GSTR + lrow * GSTR + lcol;
            float* bs = Bbuf + ((s + 1) & 1) * 128 * GSTR + lrow * GSTR + lcol;
#pragma unroll
            for (int i = 0; i < 2; i++) {
                *(float4*)(as + i * 4) = make_float4(tf32r(ra[i].x), tf32r(ra[i].y), tf32r(ra[i].z), tf32r(ra[i].w));
                *(float4*)(bs + i * 4) = make_float4(tf32r(rb[i].x), tf32r(rb[i].y), tf32r(rb[i].z), tf32r(rb[i].w));
            }
            __syncthreads();
        }
    }

    // epilogue into transposed layout: ((t*32+c)*4+q)*256 + j*16 + b
    int gid = lane >> 2, tig = lane & 3;
#pragma unroll
    for (int mf = 0; mf < 2; mf++) {
        int r0 = tM * 128 + wm * 32 + mf * 16 + gid;   // r0 & 15 == gid (0..7)
        int t0 = r0 >> 4, br = r0 & 15;
#pragma unroll
        for (int nf = 0; nf < 4; nf++) {
            int cn = tN * 128 + wn * 32 + nf * 8 + tig * 2;
            int q = cn >> 9, cc = (cn >> 4) & 31, jj = cn & 15;
            float bv0 = b1[cn] + b2[cn];
            float bv1 = b1[cn + 1] + b2[cn + 1];
            float* p = d_Xg + (((size_t)t0 * 32 + cc) * 4 + q) * 256 + jj * 16 + br;
            p[0]  = acc[mf][nf][0] + bv0;   // (r0, cn)
            p[16] = acc[mf][nf][1] + bv1;   // (r0, cn+1)
            p[8]  = acc[mf][nf][2] + bv0;   // (r0+8, cn)
            p[24] = acc[mf][nf][3] + bv1;   // (r0+8, cn+1)
        }
    }
}

// ---- logits tile: one 128x128 tile, 16 warps (32x32 each) ----
__device__ void gemm_tile_logits(float* sm, const float* __restrict__ Wout,
                                 const float* __restrict__ bout,
                                 float* __restrict__ out, int chunk, int ntile) {
    float* Abuf = sm;                      // [2][128*GSTR]
    float* Bbuf = sm + 2 * 128 * GSTR;     // [2][128*GSTR]

    int tid = threadIdx.x;
    int wid = tid >> 5, lane = tid & 31;
    int wm = wid >> 2, wn = wid & 3;
    int r8 = lane & 7, sq = lane >> 3;

    uint32_t a_off = (uint32_t)((((sq & 1) * 8 + r8) * GSTR + (sq >> 1) * 4) * 4);
    uint32_t b_off = (uint32_t)((((sq >> 1) * 8 + r8) * GSTR + (sq & 1) * 4) * 4);
    uint32_t abase0 = s2u(Abuf) + (uint32_t)(wm * 32 * GSTR * 4) + a_off;
    uint32_t bbase0 = s2u(Bbuf) + (uint32_t)(wn * 32 * GSTR * 4) + b_off;

    int lrow = tid >> 2;
    int lcol = (tid & 3) * 8;
    const float* Ap = d_H2 + (size_t)(chunk * 128 + lrow) * HSZ + lcol;
    const float* Bp = Wout + (size_t)(ntile * 128 + lrow) * HSZ + lcol;

    float4 ra[2], rb[2];
#pragma unroll
    for (int i = 0; i < 2; i++) {
        ra[i] = __ldcg((const float4*)(Ap + i * 4));   // already tf32-rounded
        rb[i] = __ldg((const float4*)(Bp + i * 4));
    }

    float acc[2][4][4];
#pragma unroll
    for (int i = 0; i < 2; i++)
#pragma unroll
        for (int j = 0; j < 4; j++)
#pragma unroll
            for (int k = 0; k < 4; k++) acc[i][j][k] = 0.f;

    {
        float* as = Abuf + lrow * GSTR + lcol;
        float* bs = Bbuf + lrow * GSTR + lcol;
#pragma unroll
        for (int i = 0; i < 2; i++) {
            *(float4*)(as + i * 4) = ra[i];
            *(float4*)(bs + i * 4) = make_float4(tf32r(rb[i].x), tf32r(rb[i].y), tf32r(rb[i].z), tf32r(rb[i].w));
        }
    }
    __syncthreads();

    for (int s = 0; s < 16; s++) {
        if (s < 15) {
            int k0 = (s + 1) * 32;
#pragma unroll
            for (int i = 0; i < 2; i++) {
                ra[i] = __ldcg((const float4*)(Ap + k0 + i * 4));
                rb[i] = __ldg((const float4*)(Bp + k0 + i * 4));
            }
        }
        uint32_t asb = abase0 + (uint32_t)((s & 1) * 128 * GSTR * 4);
        uint32_t bsb = bbase0 + (uint32_t)((s & 1) * 128 * GSTR * 4);
#pragma unroll
        for (int k8 = 0; k8 < 32; k8 += 8) {
            uint32_t af[2][4], bf[2][4];
#pragma unroll
            for (int mf = 0; mf < 2; mf++)
                ldsm4(af[mf], asb + (uint32_t)(mf * 16 * GSTR * 4) + (uint32_t)(k8 * 4));
            ldsm4(bf[0], bsb + (uint32_t)(k8 * 4));
            ldsm4(bf[1], bsb + (uint32_t)(16 * GSTR * 4) + (uint32_t)(k8 * 4));
#pragma unroll
            for (int mf = 0; mf < 2; mf++) {
                mma8(acc[mf][0], af[mf], &bf[0][0]);
                mma8(acc[mf][1], af[mf], &bf[0][2]);
                mma8(acc[mf][2], af[mf], &bf[1][0]);
                mma8(acc[mf][3], af[mf], &bf[1][2]);
            }
        }
        if (s < 15) {
            __syncthreads();
            float* as = Abuf + ((s + 1) & 1) * 128 * GSTR + lrow * GSTR + lcol;
            float* bs = Bbuf + ((s + 1) & 1) * 128 * GSTR + lrow * GSTR + lcol;
#pragma unroll
            for (int i = 0; i < 2; i++) {
                *(float4*)(as + i * 4) = ra[i];
                *(float4*)(bs + i * 4) = make_float4(tf32r(rb[i].x), tf32r(rb[i].y), tf32r(rb[i].z), tf32r(rb[i].w));
            }
            __syncthreads();
        }
    }

    // epilogue: row r = t*B+b  ->  out row b*T+t
    int gid = lane >> 2, tig = lane & 3;
#pragma unroll
    for (int mf = 0; mf < 2; mf++) {
        int r0 = chunk * 128 + wm * 32 + mf * 16 + gid;
        int r1 = r0 + 8;
        int o0 = (r0 & 15) * TSZ + (r0 >> 4);
        int o1 = (r1 & 15) * TSZ + (r1 >> 4);
#pragma unroll
        for (int nf = 0; nf < 4; nf++) {
            int cn = ntile * 128 + wn * 32 + nf * 8 + tig * 2;
            float bv0 = bout[cn], bv1 = bout[cn + 1];
            *(float2*)(out + (size_t)o0 * VSZ + cn) = make_float2(acc[mf][nf][0] + bv0, acc[mf][nf][1] + bv1);
            *(float2*)(out + (size_t)o1 * VSZ + cn) = make_float2(acc[mf][nf][2] + bv0, acc[mf][nf][3] + bv1);
        }
    }
}

__global__ __launch_bounds__(512, 1)
void k_fused(const float* __restrict__ h0, const float* __restrict__ c0,
             const float* __restrict__ W_hh, const float* __restrict__ W_ih,
             const float* __restrict__ b_ih, const float* __restrict__ b_hh,
             const float* __restrict__ W_out, const float* __restrict__ b_out,
             const float* __restrict__ emb, float* __restrict__ out) {
    extern __shared__ float sm[];
    __shared__ int jslot;
    int tid = threadIdx.x;

    if (blockIdx.x < NRNN) {
        // -------- recurrence role (32 CTAs, 16 warps) --------
        float* Wsh = sm;                                  // [64][516]
        float* hsh = sm + 64 * WS_STRIDE;                 // [16][524]
        float* red = hsh + 16 * HS_STRIDE;                // [4][64][16]

        int c = blockIdx.x;
        int wid = tid >> 5, lane = tid & 31, gid = lane >> 2, tig = lane & 3;
        int r8 = lane & 7, sq = lane >> 3;
        int mg = wid >> 2, kq = wid & 3;                  // M-group, K-quarter

        uint32_t w_off = (uint32_t)((((sq & 1) * 8 + r8) * WS_STRIDE + (sq >> 1) * 4) * 4);
        uint32_t h_off = (uint32_t)((((sq >> 1) * 8 + r8) * HS_STRIDE + (sq & 1) * 4) * 4);
        uint32_t wbase = s2u(Wsh) + w_off + (uint32_t)(mg * 16 * WS_STRIDE * 4);
        uint32_t hbase = s2u(hsh) + h_off;

        for (int i = tid; i < 64 * HSZ; i += 512) {
            int lr = i >> 9, k = i & 511;
            int grow = (lr >> 4) * HSZ + c * 16 + (lr & 15);
            Wsh[lr * WS_STRIDE + k] = tf32r(W_hh[(size_t)grow * HSZ + k]);
        }
        __syncthreads();

        int j = tid >> 4, b = tid & 15, dim = c * 16 + (j & 15);
        float creg = 0.f;
        if (tid < 256) creg = c0[b * HSZ + dim];
        int kbase = kq * 128;
        // transposed gate base for (c, j, b)
        const float* xgbase = d_Xg + ((size_t)c * 4) * 256 + (j & 15) * 16 + b;

        for (int t = 0; t < TSZ; t++) {
            // wait for the Xg row-block of this 8-step window (pool-produced)
            if ((t & 7) == 0) {
                if (tid == 0) {
                    while (ld_acq(&d_xgc[t >> 3]) < 16u) __nanosleep(64);
                }
                __syncthreads();
            }

            const float* hsrc = (t == 0) ? h0 : (d_H2 + (size_t)(t - 1) * (BSZ * HSZ));
            float gx0 = 0.f, gx1 = 0.f, gx2 = 0.f, gx3 = 0.f;
            if (tid < 256) {
                const float* xg = xgbase + (size_t)t * 32768;   // 32*4*256
                gx0 = __ldcs(xg);
                gx1 = __ldcs(xg + 256);
                gx2 = __ldcs(xg + 512);
                gx3 = __ldcs(xg + 768);
            }

            // stage h: 2048 float4 words, 512 threads -> 4 each
            for (int i4 = tid; i4 < (BSZ * HSZ) / 4; i4 += 512) {
                int bb = i4 >> 7;
                int kk = (i4 & 127) * 4;
                float4 v = __ldcg((const float4*)(hsrc + bb * HSZ + kk));
                v.x = tf32r(v.x); v.y = tf32r(v.y); v.z = tf32r(v.z); v.w = tf32r(v.w);
                *(float4*)&hsh[bb * HS_STRIDE + kk] = v;
            }
            __syncthreads();

            // MMA: warp = (M-group mg: 16 gate rows) x (K-quarter kq: 128 k)
            float acc[2][4];
#pragma unroll
            for (int nf = 0; nf < 2; nf++)
#pragma unroll
                for (int r = 0; r < 4; r++) acc[nf][r] = 0.f;
#pragma unroll
            for (int kf = 0; kf < 16; kf++) {
                int k0 = kbase + kf * 8;
                uint32_t bfr[4], af[4];
                ldsm4(bfr, hbase + (uint32_t)(k0 * 4));
                ldsm4(af, wbase + (uint32_t)(k0 * 4));
                mma8(acc[0], af, &bfr[0]);
                mma8(acc[1], af, &bfr[2]);
            }
            {
                int lr = mg * 16 + gid;
#pragma unroll
                for (int nf = 0; nf < 2; nf++) {
                    int bb = nf * 8 + tig * 2;
                    *(float2*)&red[(kq * 64 + lr) * 16 + bb]     = make_float2(acc[nf][0], acc[nf][1]);
                    *(float2*)&red[(kq * 64 + lr + 8) * 16 + bb] = make_float2(acc[nf][2], acc[nf][3]);
                }
            }
            __syncthreads();

            if (tid < 256) {
                float g[4] = {gx0, gx1, gx2, gx3};
#pragma unroll
                for (int q = 0; q < 4; q++) {
                    int lr = q * 16 + j;
#pragma unroll
                    for (int w = 0; w < 4; w++) g[q] += red[(w * 64 + lr) * 16 + b];
                }
                float ig = sigf(g[0]), fg = sigf(g[1]), gg = tanhf(g[2]), og = sigf(g[3]);
                creg = fg * creg + ig * gg;
                float h2 = og * tanhf(creg);

                d_H2[(size_t)(t * BSZ + b) * HSZ + dim] = tf32r(h2);
                if (t == TSZ - 1) {
                    out[OUT_HF + b * HSZ + dim] = h2;     // exact final states
                    out[OUT_CF + b * HSZ + dim] = creg;
                }
            }
            __syncthreads();

            // 4-way split barrier: CTA group (c>>3) increments its own word
            if (tid == 0) {
                __threadfence();
                atomicAdd(&d_bar4[(c >> 3) << 5], 1u);
            }
            if (t < TSZ - 1) {
                unsigned target = 8u * (unsigned)(t + 1);
                if (tid < 4) {
                    while (ld_acq(&d_bar4[tid << 5]) < target) { }
                }
                __syncthreads();
                if (c == 0 && tid == 0 && ((t + 1) & 7) == 0) {
                    __threadfence();
                    *(volatile unsigned*)&d_chunk = (unsigned)((t + 1) >> 3);
                }
            }
        }

        // final chunk publication (chunk 15)
        if (c == 0) {
            if (tid < 4) {
                while (ld_acq(&d_bar4[tid << 5]) < 8u * (unsigned)TSZ) { }
            }
            __syncthreads();
            if (tid == 0) {
                __threadfence();
                *(volatile unsigned*)&d_chunk = (unsigned)NCHUNK;
            }
        }
        __syncthreads();
        // fall through: join consumer pool for the tail
    }

    // -------- job pool: gathers, then Xg tiles, then logits tiles --------
    for (;;) {
        __syncthreads();
        if (tid == 0) jslot = (int)atomicAdd(&d_job, 1u);
        __syncthreads();
        int jb = jslot;
        if (jb >= NTOT) break;
        if (jb < NGATH) {
            gather_job(emb, jb);
            __syncthreads();
            if (tid == 0) { __threadfence(); st_rel(&d_gc[jb], 1u); }
        } else if (jb < NGATH + NXG) {
            int q = jb - NGATH;
            int tM = q >> 4, tN = q & 15;
            if (tid == 0) {
                while (ld_acq(&d_gc[tM]) == 0u) __nanosleep(64);
            }
            __syncthreads();
            gemm_tile_xg(sm, W_ih, b_ih, b_hh, tM, tN);
            __syncthreads();
            if (tid == 0) { __threadfence(); atomicAdd(&d_xgc[tM], 1u); }
        } else {
            int q = jb - NGATH - NXG;
            int chunk = q / NT, ntile = q % NT;
            if (tid == 0) {
                while (ld_acq(&d_chunk) <= (unsigned)chunk) __nanosleep(128);
            }
            __syncthreads();
            gemm_tile_logits(sm, W_out, b_out, out, chunk, ntile);
        }
    }
}

// ---------------- launch ----------------
extern "C" void kernel_launch(void* const* d_in, const int* in_sizes, int n_in,
                              void* d_out, int out_size) {
    (void)in_sizes; (void)n_in; (void)out_size;
    const float* h0    = (const float*)d_in[1];
    const float* c0    = (const float*)d_in[2];
    const void*  tgt   = d_in[3];
    const float* emb   = (const float*)d_in[4];
    const float* W_ih  = (const float*)d_in[5];
    const float* W_hh  = (const float*)d_in[6];
    const float* b_ih  = (const float*)d_in[7];
    const float* b_hh  = (const float*)d_in[8];
    const float* W_out = (const float*)d_in[9];
    const float* b_out = (const float*)d_in[10];
    float* out = (float*)d_out;

    cudaFuncSetAttribute(k_fused, cudaFuncAttributeMaxDynamicSharedMemorySize, RNN_SMEM);

    k_prep<<<1, 256>>>(tgt);
    k_fused<<<NGRID, 512, RNN_SMEM>>>(h0, c0, W_hh, W_ih, b_ih, b_hh, W_out, b_out, emb, out);
}

// round 17
// speedup vs baseline: 1.8400x; 1.0057x over previous
#include <cuda_runtime.h>
#include <cstdint>

// Problem constants
#define VSZ   32000
#define HSZ   512
#define BSZ   16
#define TSZ   128
#define G4    2048           // 4*H
#define NROW  2048           // T*B rows
#define OUT_HF 65536000      // B*T*V
#define OUT_CF 65544192      // + B*H

#define NRNN   32            // recurrence CTAs
#define NGRID  148
#define NT     (VSZ / 128)   // 250 logits N-tiles
#define NCHUNK 16            // 16 chunks of 8 timesteps (128 rows)
#define NGATH  16            // 16 gather jobs (128 rows each)
#define NXG    256           // 16 tM x 16 tN Xg tiles
#define NJOBS  (NCHUNK * NT) // 4000 logits jobs
#define NTOT   (NGATH + NXG + NJOBS)

// ---------------- device scratch (no allocations allowed) ----------------
__device__ int      d_toks[NROW];
__device__ float    d_X [(size_t)NROW * HSZ];  // relu(emb[tok])       4 MB
// transposed gates: idx = ((t*32 + c)*4 + q)*256 + j*16 + b   (16 MB)
__device__ float    d_Xg[(size_t)TSZ * 32 * 4 * 256];
__device__ float    d_H2[(size_t)NROW * HSZ];  // all h2 (tf32-rounded) 4 MB
__device__ __align__(128) unsigned d_bar4[128];// 4 barrier words, 128B apart
__device__ unsigned d_gc[16];                  // gather-done flags
__device__ unsigned d_xgc[16];                 // per-tM Xg tile counters
__device__ unsigned d_chunk;                   // published chunk count
__device__ unsigned d_job;                     // dynamic job counter

// ---------------- helpers ----------------
__device__ __forceinline__ float tf32r(float x) {
    uint32_t u;
    asm("cvt.rna.tf32.f32 %0, %1;" : "=r"(u) : "f"(x));
    return __uint_as_float(u);
}
__device__ __forceinline__ uint32_t fbits(float x) { return __float_as_uint(x); }
__device__ __forceinline__ uint32_t s2u(const void* p) {
    return (uint32_t)__cvta_generic_to_shared(p);
}

__device__ __forceinline__ void mma8(float* d, const uint32_t* a, const uint32_t* b) {
    asm volatile(
        "mma.sync.aligned.m16n8k8.row.col.f32.tf32.tf32.f32 "
        "{%0,%1,%2,%3}, {%4,%5,%6,%7}, {%8,%9}, {%0,%1,%2,%3};"
        : "+f"(d[0]), "+f"(d[1]), "+f"(d[2]), "+f"(d[3])
        : "r"(a[0]), "r"(a[1]), "r"(a[2]), "r"(a[3]), "r"(b[0]), "r"(b[1]));
}

__device__ __forceinline__ void ldsm4(uint32_t* r, uint32_t addr) {
    asm volatile("ldmatrix.sync.aligned.m8n8.x4.shared.b16 {%0,%1,%2,%3}, [%4];"
                 : "=r"(r[0]), "=r"(r[1]), "=r"(r[2]), "=r"(r[3]) : "r"(addr));
}

__device__ __forceinline__ float sigf(float x) { return 1.0f / (1.0f + __expf(-x)); }

__device__ __forceinline__ unsigned ld_acq(const unsigned* p) {
    unsigned v;
    asm volatile("ld.global.acquire.gpu.u32 %0, [%1];" : "=r"(v) : "l"(p) : "memory");
    return v;
}
__device__ __forceinline__ void st_rel(unsigned* p, unsigned v) {
    asm volatile("st.global.release.gpu.u32 [%0], %1;" :: "l"(p), "r"(v) : "memory");
}
__device__ __forceinline__ void red_rel_add(unsigned* p, unsigned v) {
    asm volatile("red.release.gpu.global.add.u32 [%0], %1;" :: "l"(p), "r"(v) : "memory");
}
__device__ __forceinline__ void stcs2(float* p, float2 v) {
    asm volatile("st.global.cs.v2.f32 [%0], {%1, %2};" :: "l"(p), "f"(v.x), "f"(v.y) : "memory");
}

// ---------------- kernel 0: token prep (+ dtype detect, + counter reset) ----
__global__ void k_prep(const void* tgt) {
    __shared__ int nz;
    if (threadIdx.x == 0) nz = 0;
    __syncthreads();
    const unsigned* w = (const unsigned*)tgt;
    for (int i = threadIdx.x; i < 1024; i += blockDim.x)
        if (w[2 * i + 1] != 0u) atomicOr(&nz, 1);
    __syncthreads();
    bool is64 = (nz == 0);
    const long long* p64 = (const long long*)tgt;
    const int*       p32 = (const int*)tgt;
    for (int idx = threadIdx.x; idx < NROW; idx += blockDim.x) {
        int t = idx >> 4, b = idx & 15;
        int tok;
        if (t == 0) tok = 1;                      // BOS
        else {
            int s = b * TSZ + (t - 1);
            tok = is64 ? (int)p64[s] : p32[s];
        }
        d_toks[idx] = tok;
    }
    if (threadIdx.x < 128) d_bar4[threadIdx.x] = 0u;
    if (threadIdx.x < 16)  { d_gc[threadIdx.x] = 0u; d_xgc[threadIdx.x] = 0u; }
    if (threadIdx.x == 0)  { d_chunk = 0u; d_job = 0u; }
}

// ================== fused persistent kernel (512 threads / CTA) ==========
#define WS_STRIDE 516
#define HS_STRIDE 524
#define RNN_SMEM ((64 * WS_STRIDE + 16 * HS_STRIDE + 4 * 64 * 16) * 4)
#define GSTR 36   // GEMM smem row stride (floats)

// ---- gather job g: rows [g*128, g*128+128) of X = relu(emb[tok]) --------
__device__ void gather_job(const float* __restrict__ emb, int g) {
    int tid = threadIdx.x;
    for (int i = tid; i < 128 * 128; i += 512) {       // 16384 float4
        int r = g * 128 + (i >> 7);
        int kk = (i & 127);
        int tok = d_toks[r];
        float4 v = __ldg((const float4*)(emb + (size_t)tok * HSZ) + kk);
        v.x = fmaxf(v.x, 0.f); v.y = fmaxf(v.y, 0.f);
        v.z = fmaxf(v.z, 0.f); v.w = fmaxf(v.w, 0.f);
        ((float4*)(d_X + (size_t)r * HSZ))[kk] = v;
    }
}

// ---- Xg tile (tM,tN): rows tM*128..+128, cols tN*128..+128, transposed out
// d_X written inside this kernel -> coherent loads (__ldcg), NOT __ldg.
__device__ void gemm_tile_xg(float* sm, const float* __restrict__ Wih,
                             const float* __restrict__ b1, const float* __restrict__ b2,
                             int tM, int tN) {
    float* Abuf = sm;                      // [2][128*GSTR]
    float* Bbuf = sm + 2 * 128 * GSTR;     // [2][128*GSTR]

    int tid = threadIdx.x;
    int wid = tid >> 5, lane = tid & 31;
    int wm = wid >> 2, wn = wid & 3;       // 4 x 4 warps -> 32 x 32 tiles
    int r8 = lane & 7, sq = lane >> 3;

    uint32_t a_off = (uint32_t)((((sq & 1) * 8 + r8) * GSTR + (sq >> 1) * 4) * 4);
    uint32_t b_off = (uint32_t)((((sq >> 1) * 8 + r8) * GSTR + (sq & 1) * 4) * 4);
    uint32_t abase0 = s2u(Abuf) + (uint32_t)(wm * 32 * GSTR * 4) + a_off;
    uint32_t bbase0 = s2u(Bbuf) + (uint32_t)(wn * 32 * GSTR * 4) + b_off;

    int lrow = tid >> 2;                   // 0..127
    int lcol = (tid & 3) * 8;              // 0,8,16,24
    const float* Ap = d_X + (size_t)(tM * 128 + lrow) * HSZ + lcol;
    const float* Bp = Wih + (size_t)(tN * 128 + lrow) * HSZ + lcol;

    float4 ra[2], rb[2];
#pragma unroll
    for (int i = 0; i < 2; i++) {
        ra[i] = __ldcg((const float4*)(Ap + i * 4));
        rb[i] = __ldg((const float4*)(Bp + i * 4));
    }

    float acc[2][4][4];
#pragma unroll
    for (int i = 0; i < 2; i++)
#pragma unroll
        for (int j = 0; j < 4; j++)
#pragma unroll
            for (int k = 0; k < 4; k++) acc[i][j][k] = 0.f;

    {
        float* as = Abuf + lrow * GSTR + lcol;
        float* bs = Bbuf + lrow * GSTR + lcol;
#pragma unroll
        for (int i = 0; i < 2; i++) {
            *(float4*)(as + i * 4) = make_float4(tf32r(ra[i].x), tf32r(ra[i].y), tf32r(ra[i].z), tf32r(ra[i].w));
            *(float4*)(bs + i * 4) = make_float4(tf32r(rb[i].x), tf32r(rb[i].y), tf32r(rb[i].z), tf32r(rb[i].w));
        }
    }
    __syncthreads();

    for (int s = 0; s < 16; s++) {
        if (s < 15) {
            int k0 = (s + 1) * 32;
#pragma unroll
            for (int i = 0; i < 2; i++) {
                ra[i] = __ldcg((const float4*)(Ap + k0 + i * 4));
                rb[i] = __ldg((const float4*)(Bp + k0 + i * 4));
            }
        }
        uint32_t asb = abase0 + (uint32_t)((s & 1) * 128 * GSTR * 4);
        uint32_t bsb = bbase0 + (uint32_t)((s & 1) * 128 * GSTR * 4);
#pragma unroll
        for (int k8 = 0; k8 < 32; k8 += 8) {
            uint32_t af[2][4], bf[2][4];
#pragma unroll
            for (int mf = 0; mf < 2; mf++)
                ldsm4(af[mf], asb + (uint32_t)(mf * 16 * GSTR * 4) + (uint32_t)(k8 * 4));
            ldsm4(bf[0], bsb + (uint32_t)(k8 * 4));
            ldsm4(bf[1], bsb + (uint32_t)(16 * GSTR * 4) + (uint32_t)(k8 * 4));
#pragma unroll
            for (int mf = 0; mf < 2; mf++) {
                mma8(acc[mf][0], af[mf], &bf[0][0]);
                mma8(acc[mf][1], af[mf], &bf[0][2]);
                mma8(acc[mf][2], af[mf], &bf[1][0]);
                mma8(acc[mf][3], af[mf], &bf[1][2]);
            }
        }
        if (s < 15) {
            __syncthreads();
            float* as = Abuf + ((s + 1) & 1) * 128 * GSTR + lrow * GSTR + lcol;
            float* bs = Bbuf + ((s + 1) & 1) * 128 * GSTR + lrow * GSTR + lcol;
#pragma unroll
            for (int i = 0; i < 2; i++) {
                *(float4*)(as + i * 4) = make_float4(tf32r(ra[i].x), tf32r(ra[i].y), tf32r(ra[i].z), tf32r(ra[i].w));
                *(float4*)(bs + i * 4) = make_float4(tf32r(rb[i].x), tf32r(rb[i].y), tf32r(rb[i].z), tf32r(rb[i].w));
            }
            __syncthreads();
        }
    }

    // epilogue into transposed layout: ((t*32+c)*4+q)*256 + j*16 + b
    int gid = lane >> 2, tig = lane & 3;
#pragma unroll
    for (int mf = 0; mf < 2; mf++) {
        int r0 = tM * 128 + wm * 32 + mf * 16 + gid;   // r0 & 15 == gid (0..7)
        int t0 = r0 >> 4, br = r0 & 15;
#pragma unroll
        for (int nf = 0; nf < 4; nf++) {
            int cn = tN * 128 + wn * 32 + nf * 8 + tig * 2;
            int q = cn >> 9, cc = (cn >> 4) & 31, jj = cn & 15;
            float bv0 = b1[cn] + b2[cn];
            float bv1 = b1[cn + 1] + b2[cn + 1];
            float* p = d_Xg + (((size_t)t0 * 32 + cc) * 4 + q) * 256 + jj * 16 + br;
            p[0]  = acc[mf][nf][0] + bv0;   // (r0, cn)
            p[16] = acc[mf][nf][1] + bv1;   // (r0, cn+1)
            p[8]  = acc[mf][nf][2] + bv0;   // (r0+8, cn)
            p[24] = acc[mf][nf][3] + bv1;   // (r0+8, cn+1)
        }
    }
}

// ---- logits tile: one 128x128 tile, 16 warps (32x32 each) ----
__device__ void gemm_tile_logits(float* sm, const float* __restrict__ Wout,
                                 const float* __restrict__ bout,
                                 float* __restrict__ out, int chunk, int ntile) {
    float* Abuf = sm;                      // [2][128*GSTR]
    float* Bbuf = sm + 2 * 128 * GSTR;     // [2][128*GSTR]

    int tid = threadIdx.x;
    int wid = tid >> 5, lane = tid & 31;
    int wm = wid >> 2, wn = wid & 3;
    int r8 = lane & 7, sq = lane >> 3;

    uint32_t a_off = (uint32_t)((((sq & 1) * 8 + r8) * GSTR + (sq >> 1) * 4) * 4);
    uint32_t b_off = (uint32_t)((((sq >> 1) * 8 + r8) * GSTR + (sq & 1) * 4) * 4);
    uint32_t abase0 = s2u(Abuf) + (uint32_t)(wm * 32 * GSTR * 4) + a_off;
    uint32_t bbase0 = s2u(Bbuf) + (uint32_t)(wn * 32 * GSTR * 4) + b_off;

    int lrow = tid >> 2;
    int lcol = (tid & 3) * 8;
    const float* Ap = d_H2 + (size_t)(chunk * 128 + lrow) * HSZ + lcol;
    const float* Bp = Wout + (size_t)(ntile * 128 + lrow) * HSZ + lcol;

    float4 ra[2], rb[2];
#pragma unroll
    for (int i = 0; i < 2; i++) {
        ra[i] = __ldcg((const float4*)(Ap + i * 4));   // already tf32-rounded
        rb[i] = __ldg((const float4*)(Bp + i * 4));
    }

    float acc[2][4][4];
#pragma unroll
    for (int i = 0; i < 2; i++)
#pragma unroll
        for (int j = 0; j < 4; j++)
#pragma unroll
            for (int k = 0; k < 4; k++) acc[i][j][k] = 0.f;

    {
        float* as = Abuf + lrow * GSTR + lcol;
        float* bs = Bbuf + lrow * GSTR + lcol;
#pragma unroll
        for (int i = 0; i < 2; i++) {
            *(float4*)(as + i * 4) = ra[i];
            *(float4*)(bs + i * 4) = make_float4(tf32r(rb[i].x), tf32r(rb[i].y), tf32r(rb[i].z), tf32r(rb[i].w));
        }
    }
    __syncthreads();

    for (int s = 0; s < 16; s++) {
        if (s < 15) {
            int k0 = (s + 1) * 32;
#pragma unroll
            for (int i = 0; i < 2; i++) {
                ra[i] = __ldcg((const float4*)(Ap + k0 + i * 4));
                rb[i] = __ldg((const float4*)(Bp + k0 + i * 4));
            }
        }
        uint32_t asb = abase0 + (uint32_t)((s & 1) * 128 * GSTR * 4);
        uint32_t bsb = bbase0 + (uint32_t)((s & 1) * 128 * GSTR * 4);
#pragma unroll
        for (int k8 = 0; k8 < 32; k8 += 8) {
            uint32_t af[2][4], bf[2][4];
#pragma unroll
            for (int mf = 0; mf < 2; mf++)
                ldsm4(af[mf], asb + (uint32_t)(mf * 16 * GSTR * 4) + (uint32_t)(k8 * 4));
            ldsm4(bf[0], bsb + (uint32_t)(k8 * 4));
            ldsm4(bf[1], bsb + (uint32_t)(16 * GSTR * 4) + (uint32_t)(k8 * 4));
#pragma unroll
            for (int mf = 0; mf < 2; mf++) {
                mma8(acc[mf][0], af[mf], &bf[0][0]);
                mma8(acc[mf][1], af[mf], &bf[0][2]);
                mma8(acc[mf][2], af[mf], &bf[1][0]);
                mma8(acc[mf][3], af[mf], &bf[1][2]);
            }
        }
        if (s < 15) {
            __syncthreads();
            float* as = Abuf + ((s + 1) & 1) * 128 * GSTR + lrow * GSTR + lcol;
            float* bs = Bbuf + ((s + 1) & 1) * 128 * GSTR + lrow * GSTR + lcol;
#pragma unroll
            for (int i = 0; i < 2; i++) {
                *(float4*)(as + i * 4) = ra[i];
                *(float4*)(bs + i * 4) = make_float4(tf32r(rb[i].x), tf32r(rb[i].y), tf32r(rb[i].z), tf32r(rb[i].w));
            }
            __syncthreads();
        }
    }

    // epilogue: row r = t*B+b -> out row b*T+t ; streaming stores (out is
    // write-once, never re-read -> keep it out of L2 so W_out stays resident)
    int gid = lane >> 2, tig = lane & 3;
#pragma unroll
    for (int mf = 0; mf < 2; mf++) {
        int r0 = chunk * 128 + wm * 32 + mf * 16 + gid;
        int r1 = r0 + 8;
        int o0 = (r0 & 15) * TSZ + (r0 >> 4);
        int o1 = (r1 & 15) * TSZ + (r1 >> 4);
#pragma unroll
        for (int nf = 0; nf < 4; nf++) {
            int cn = ntile * 128 + wn * 32 + nf * 8 + tig * 2;
            float bv0 = bout[cn], bv1 = bout[cn + 1];
            stcs2(out + (size_t)o0 * VSZ + cn, make_float2(acc[mf][nf][0] + bv0, acc[mf][nf][1] + bv1));
            stcs2(out + (size_t)o1 * VSZ + cn, make_float2(acc[mf][nf][2] + bv0, acc[mf][nf][3] + bv1));
        }
    }
}

__global__ __launch_bounds__(512, 1)
void k_fused(const float* __restrict__ h0, const float* __restrict__ c0,
             const float* __restrict__ W_hh, const float* __restrict__ W_ih,
             const float* __restrict__ b_ih, const float* __restrict__ b_hh,
             const float* __restrict__ W_out, const float* __restrict__ b_out,
             const float* __restrict__ emb, float* __restrict__ out) {
    extern __shared__ float sm[];
    __shared__ int jslot;
    int tid = threadIdx.x;

    if (blockIdx.x < NRNN) {
        // -------- recurrence role (32 CTAs, 16 warps) --------
        float* Wsh = sm;                                  // [64][516]
        float* hsh = sm + 64 * WS_STRIDE;                 // [16][524]
        float* red = hsh + 16 * HS_STRIDE;                // [4][64][16]

        int c = blockIdx.x;
        int wid = tid >> 5, lane = tid & 31, gid = lane >> 2, tig = lane & 3;
        int r8 = lane & 7, sq = lane >> 3;
        int mg = wid >> 2, kq = wid & 3;                  // M-group, K-quarter

        uint32_t w_off = (uint32_t)((((sq & 1) * 8 + r8) * WS_STRIDE + (sq >> 1) * 4) * 4);
        uint32_t h_off = (uint32_t)((((sq >> 1) * 8 + r8) * HS_STRIDE + (sq & 1) * 4) * 4);
        uint32_t wbase = s2u(Wsh) + w_off + (uint32_t)(mg * 16 * WS_STRIDE * 4);
        uint32_t hbase = s2u(hsh) + h_off;

        for (int i = tid; i < 64 * HSZ; i += 512) {
            int lr = i >> 9, k = i & 511;
            int grow = (lr >> 4) * HSZ + c * 16 + (lr & 15);
            Wsh[lr * WS_STRIDE + k] = tf32r(W_hh[(size_t)grow * HSZ + k]);
        }
        __syncthreads();

        int j = tid >> 4, b = tid & 15, dim = c * 16 + (j & 15);
        float creg = 0.f;
        if (tid < 256) creg = c0[b * HSZ + dim];
        int kbase = kq * 128;
        // transposed gate base for (c, j, b)
        const float* xgbase = d_Xg + ((size_t)c * 4) * 256 + (j & 15) * 16 + b;

        for (int t = 0; t < TSZ; t++) {
            // wait for the Xg row-block of this 8-step window (pool-produced)
            if ((t & 7) == 0) {
                if (tid == 0) {
                    while (ld_acq(&d_xgc[t >> 3]) < 16u) __nanosleep(64);
                }
                __syncthreads();
            }

            const float* hsrc = (t == 0) ? h0 : (d_H2 + (size_t)(t - 1) * (BSZ * HSZ));
            float gx0 = 0.f, gx1 = 0.f, gx2 = 0.f, gx3 = 0.f;
            if (tid < 256) {
                const float* xg = xgbase + (size_t)t * 32768;   // 32*4*256
                gx0 = __ldcs(xg);
                gx1 = __ldcs(xg + 256);
                gx2 = __ldcs(xg + 512);
                gx3 = __ldcs(xg + 768);
            }

            // stage h: 2048 float4 words, 512 threads -> 4 each
            for (int i4 = tid; i4 < (BSZ * HSZ) / 4; i4 += 512) {
                int bb = i4 >> 7;
                int kk = (i4 & 127) * 4;
                float4 v = __ldcg((const float4*)(hsrc + bb * HSZ + kk));
                v.x = tf32r(v.x); v.y = tf32r(v.y); v.z = tf32r(v.z); v.w = tf32r(v.w);
                *(float4*)&hsh[bb * HS_STRIDE + kk] = v;
            }
            __syncthreads();

            // MMA: warp = (M-group mg: 16 gate rows) x (K-quarter kq: 128 k)
            float acc[2][4];
#pragma unroll
            for (int nf = 0; nf < 2; nf++)
#pragma unroll
                for (int r = 0; r < 4; r++) acc[nf][r] = 0.f;
#pragma unroll
            for (int kf = 0; kf < 16; kf++) {
                int k0 = kbase + kf * 8;
                uint32_t bfr[4], af[4];
                ldsm4(bfr, hbase + (uint32_t)(k0 * 4));
                ldsm4(af, wbase + (uint32_t)(k0 * 4));
                mma8(acc[0], af, &bfr[0]);
                mma8(acc[1], af, &bfr[2]);
            }
            {
                int lr = mg * 16 + gid;
#pragma unroll
                for (int nf = 0; nf < 2; nf++) {
                    int bb = nf * 8 + tig * 2;
                    *(float2*)&red[(kq * 64 + lr) * 16 + bb]     = make_float2(acc[nf][0], acc[nf][1]);
                    *(float2*)&red[(kq * 64 + lr + 8) * 16 + bb] = make_float2(acc[nf][2], acc[nf][3]);
                }
            }
            __syncthreads();

            if (tid < 256) {
                float g[4] = {gx0, gx1, gx2, gx3};
#pragma unroll
                for (int q = 0; q < 4; q++) {
                    int lr = q * 16 + j;
#pragma unroll
                    for (int w = 0; w < 4; w++) g[q] += red[(w * 64 + lr) * 16 + b];
                }
                float ig = sigf(g[0]), fg = sigf(g[1]), gg = tanhf(g[2]), og = sigf(g[3]);
                creg = fg * creg + ig * gg;
                float h2 = og * tanhf(creg);

                d_H2[(size_t)(t * BSZ + b) * HSZ + dim] = tf32r(h2);
                if (t == TSZ - 1) {
                    out[OUT_HF + b * HSZ + dim] = h2;     // exact final states
                    out[OUT_CF + b * HSZ + dim] = creg;
                }
            }
            __syncthreads();

            // 4-way split barrier: release-atomic folds the fence into the op
            // (stores -> syncthreads -> release-red -> acquire-poll chain)
            if (tid == 0) red_rel_add(&d_bar4[(c >> 3) << 5], 1u);
            if (t < TSZ - 1) {
                unsigned target = 8u * (unsigned)(t + 1);
                if (tid < 4) {
                    while (ld_acq(&d_bar4[tid << 5]) < target) { }
                }
                __syncthreads();
                if (c == 0 && tid == 0 && ((t + 1) & 7) == 0)
                    st_rel(&d_chunk, (unsigned)((t + 1) >> 3));
            }
        }

        // final chunk publication (chunk 15)
        if (c == 0) {
            if (tid < 4) {
                while (ld_acq(&d_bar4[tid << 5]) < 8u * (unsigned)TSZ) { }
            }
            __syncthreads();
            if (tid == 0) st_rel(&d_chunk, (unsigned)NCHUNK);
        }
        __syncthreads();
        // fall through: join consumer pool for the tail
    }

    // -------- job pool: gathers, then Xg tiles, then logits tiles --------
    for (;;) {
        __syncthreads();
        if (tid == 0) jslot = (int)atomicAdd(&d_job, 1u);
        __syncthreads();
        int jb = jslot;
        if (jb >= NTOT) break;
        if (jb < NGATH) {
            gather_job(emb, jb);
            __syncthreads();
            if (tid == 0) st_rel(&d_gc[jb], 1u);
        } else if (jb < NGATH + NXG) {
            int q = jb - NGATH;
            int tM = q >> 4, tN = q & 15;
            if (tid == 0) {
                while (ld_acq(&d_gc[tM]) == 0u) __nanosleep(64);
            }
            __syncthreads();
            gemm_tile_xg(sm, W_ih, b_ih, b_hh, tM, tN);
            __syncthreads();
            if (tid == 0) red_rel_add(&d_xgc[tM], 1u);
        } else {
            int q = jb - NGATH - NXG;
            int chunk = q / NT, ntile = q % NT;
            if (tid == 0) {
                while (ld_acq(&d_chunk) <= (unsigned)chunk) __nanosleep(128);
            }
            __syncthreads();
            gemm_tile_logits(sm, W_out, b_out, out, chunk, ntile);
        }
    }
}

// ---------------- launch ----------------
extern "C" void kernel_launch(void* const* d_in, const int* in_sizes, int n_in,
                              void* d_out, int out_size) {
    (void)in_sizes; (void)n_in; (void)out_size;
    const float* h0    = (const float*)d_in[1];
    const float* c0    = (const float*)d_in[2];
    const void*  tgt   = d_in[3];
    const float* emb   = (const float*)d_in[4];
    const float* W_ih  = (const float*)d_in[5];
    const float* W_hh  = (const float*)d_in[6];
    const float* b_ih  = (const float*)d_in[7];
    const float* b_hh  = (const float*)d_in[8];
    const float* W_out = (const float*)d_in[9];
    const float* b_out = (const float*)d_in[10];
    float* out = (float*)d_out;

    cudaFuncSetAttribute(k_fused, cudaFuncAttributeMaxDynamicSharedMemorySize, RNN_SMEM);

    k_prep<<<1, 256>>>(tgt);
    k_fused<<<NGRID, 512, RNN_SMEM>>>(h0, c0, W_hh, W_ih, b_ih, b_hh, W_out, b_out, emb, out);
}